// round 11
// baseline (speedup 1.0000x reference)
#include <cuda_runtime.h>
#include <cuda_fp16.h>
#include <math.h>
#include <stdint.h>

// Problem dims
#define S_ 4
#define B_ 16
#define T_ 23        // L-1
#define L_ 24
#define H_ 512
#define E_ 512
#define G3 1536      // 3H
#define V_ 32000
#define ROWS 1472    // S*T*B
#define ROWS_PER_S 368
#define MPAD 1536    // padded rows for tensor GEMM

// Scratch (device globals; no runtime allocation allowed)
__device__ float g_gi[ROWS * G3];         // gi_seq
__device__ float g_gictx[64 * G3];        // ctx part of gi (+ b_ih)
__device__ float g_h[2][S_ * B_ * H_];    // double-buffered hidden state
__device__ float g_ctxlogit[64 * V_];     // agg @ fc_W[:,1024:] + fc_b
__device__ __half g_Wh[(size_t)V_ * 1024];   // fc_W[:, :1024] fp16
__device__ __half g_Wc[(size_t)V_ * 512];    // fc_W[:, 1024:] fp16
__device__ __half g_Ahi[(size_t)MPAD * 1024]; // feats fp16 hi (pad rows stay zero)
__device__ __half g_Alo[(size_t)MPAD * 1024]; // feats fp16 lo
__device__ __half g_Chi[128 * 512];           // agg fp16 hi (rows 64.. stay zero)
__device__ __half g_Clo[128 * 512];           // agg fp16 lo
__device__ __half g_WihH[(size_t)S_ * G3 * 512];  // W_ih[:, :512] fp16 hi
__device__ __half g_WihL[(size_t)S_ * G3 * 512];  // W_ih[:, :512] fp16 lo
__device__ unsigned g_bar;                // scan barrier counter (reset by k_wsplit)

static __device__ __forceinline__ float sigmoidf_(float x) {
    return 1.0f / (1.0f + expf(-x));
}

__device__ __forceinline__ uint32_t smem_u32(const void* p) {
    uint32_t a;
    asm("{ .reg .u64 t; cvta.to.shared.u64 t, %1; cvt.u32.u64 %0, t; }" : "=r"(a) : "l"(p));
    return a;
}

#define CP_ASYNC16(dst, src) \
    asm volatile("cp.async.cg.shared.global [%0], [%1], 16;" :: "r"(dst), "l"(src) : "memory")
#define CP_COMMIT() asm volatile("cp.async.commit_group;" ::: "memory")

#define LDSM4(r0, r1, r2, r3, addr) \
    asm volatile("ldmatrix.sync.aligned.m8n8.x4.shared.b16 {%0,%1,%2,%3}, [%4];" \
                 : "=r"(r0), "=r"(r1), "=r"(r2), "=r"(r3) : "r"(addr))

#define MMA16816H(d, a, b0, b1) \
    asm volatile("mma.sync.aligned.m16n8k16.row.col.f32.f16.f16.f32 " \
                 "{%0,%1,%2,%3}, {%4,%5,%6,%7}, {%8,%9}, {%0,%1,%2,%3};" \
                 : "+f"((d)[0]), "+f"((d)[1]), "+f"((d)[2]), "+f"((d)[3]) \
                 : "r"((a)[0]), "r"((a)[1]), "r"((a)[2]), "r"((a)[3]), \
                   "r"(b0), "r"(b1))

// split float4 -> fp16 hi (8B) + fp16 lo (8B)
__device__ __forceinline__ void fp16_split4(float4 v, uint2& hi, uint2& lo) {
    __half h0 = __float2half(v.x), h1 = __float2half(v.y);
    __half h2 = __float2half(v.z), h3 = __float2half(v.w);
    __half l0 = __float2half(v.x - __half2float(h0));
    __half l1 = __float2half(v.y - __half2float(h1));
    __half l2 = __float2half(v.z - __half2float(h2));
    __half l3 = __float2half(v.w - __half2float(h3));
    hi.x = (uint32_t)__half_as_ushort(h0) | ((uint32_t)__half_as_ushort(h1) << 16);
    hi.y = (uint32_t)__half_as_ushort(h2) | ((uint32_t)__half_as_ushort(h3) << 16);
    lo.x = (uint32_t)__half_as_ushort(l0) | ((uint32_t)__half_as_ushort(l1) << 16);
    lo.y = (uint32_t)__half_as_ushort(l2) | ((uint32_t)__half_as_ushort(l3) << 16);
}
__device__ __forceinline__ uint2 fp16_pack4(float4 v) {
    __half h0 = __float2half(v.x), h1 = __float2half(v.y);
    __half h2 = __float2half(v.z), h3 = __float2half(v.w);
    uint2 r;
    r.x = (uint32_t)__half_as_ushort(h0) | ((uint32_t)__half_as_ushort(h1) << 16);
    r.y = (uint32_t)__half_as_ushort(h2) | ((uint32_t)__half_as_ushort(h3) << 16);
    return r;
}

// ===================== small kernels =====================
__global__ void k_onehot(float* __restrict__ out) {
    long i = (long)blockIdx.x * blockDim.x + threadIdx.x;
    if (i < (long)64 * V_) {
        int p = (int)(i / V_);
        int v = (int)(i - (long)p * V_);
        out[(size_t)p * L_ * V_ + v] = (v == 1) ? 1.0f : 0.0f;
    }
}

// gather embeddings -> g_Ahi/g_Alo fp16 (emb half of feats)
__global__ void k_gather(const int* __restrict__ input, const float* __restrict__ emb) {
    int row = blockIdx.x;
    int s = row / ROWS_PER_S;
    int rr = row - s * ROWS_PER_S;
    int t = rr >> 4;
    int b = rr & 15;
    int tok = input[(b * S_ + s) * L_ + t];
    float4 v = ((const float4*)(emb + (size_t)tok * E_))[threadIdx.x];
    uint2 hi, lo;
    fp16_split4(v, hi, lo);
    *(uint2*)(g_Ahi + (size_t)row * 1024 + threadIdx.x * 4) = hi;
    *(uint2*)(g_Alo + (size_t)row * 1024 + threadIdx.x * 4) = lo;
}

// fc_W -> g_Wh (cols<1024) and g_Wc (cols 1024:1536), fp16; also reset barrier
__global__ void k_wsplit(const float* __restrict__ fc_W) {
    long idx = (long)blockIdx.x * 256 + threadIdx.x;   // one float4 each
    if (idx == 0) g_bar = 0;
    if (idx >= (long)V_ * 384) return;
    int row = (int)(idx / 384);
    int c4 = (int)(idx - (long)row * 384);
    int col = c4 * 4;
    float4 v = *(const float4*)(fc_W + (size_t)row * G3 + col);
    uint2 h = fp16_pack4(v);
    if (col < 1024)
        *(uint2*)(g_Wh + (size_t)row * 1024 + col) = h;
    else
        *(uint2*)(g_Wc + (size_t)row * 512 + (col - 1024)) = h;
}

// W_ih[:, :512] -> fp16 hi/lo
__global__ void k_wihsplit(const float* __restrict__ W_ih) {
    int idx = blockIdx.x * 256 + threadIdx.x;   // one float4 each
    if (idx >= S_ * G3 * 128) return;
    int row = idx >> 7;
    int c4 = idx & 127;
    float4 v = *(const float4*)(W_ih + (size_t)row * 1024 + c4 * 4);
    uint2 hi, lo;
    fp16_split4(v, hi, lo);
    *(uint2*)(g_WihH + (size_t)row * 512 + c4 * 4) = hi;
    *(uint2*)(g_WihL + (size_t)row * 512 + c4 * 4) = lo;
}

// agg (64 x 512) -> fp16 hi/lo split (rows 64..127 remain zero)
__global__ void k_cprep(const float* __restrict__ agg) {
    int row = blockIdx.x;                 // 0..63
    float4 v = ((const float4*)(agg + (size_t)row * 512))[threadIdx.x];
    uint2 hi, lo;
    fp16_split4(v, hi, lo);
    *(uint2*)(g_Chi + (size_t)row * 512 + threadIdx.x * 4) = hi;
    *(uint2*)(g_Clo + (size_t)row * 512 + threadIdx.x * 4) = lo;
}

// gictx[s,b,g] = ctx[s,b,:] . W_ih[s,g,512:] + b_ih[s,g]
__global__ void k_ctx_gi(const float* __restrict__ hidden,
                         const float* __restrict__ agg,
                         const float* __restrict__ W_ih,
                         const float* __restrict__ b_ih) {
    int w = blockIdx.x * 8 + (threadIdx.x >> 5);
    int lane = threadIdx.x & 31;
    int s = w / G3;
    int g = w - s * G3;
    const float* ctx = (s == 0) ? agg : (hidden + (size_t)s * B_ * H_);
    const float* wrow = W_ih + ((size_t)(s * G3) + g) * 1024 + 512;
    float acc[16];
#pragma unroll
    for (int b = 0; b < 16; b++) acc[b] = 0.0f;
    for (int d = lane; d < 512; d += 32) {
        float wv = wrow[d];
#pragma unroll
        for (int b = 0; b < 16; b++) acc[b] += wv * ctx[b * 512 + d];
    }
    float res = 0.0f;
#pragma unroll
    for (int b = 0; b < 16; b++) {
        float v = acc[b];
#pragma unroll
        for (int off = 16; off; off >>= 1) v += __shfl_xor_sync(0xffffffffu, v, off);
        if (lane == b) res = v;
    }
    if (lane < 16)
        g_gictx[(size_t)(s * 16 + lane) * G3 + g] = res + b_ih[s * G3 + g];
}

// ===================== persistent GRU scan =====================
#define WPAD 1544
#define SCAN_SMEM ((16 * WPAD + 16 * 516) * 4)

__global__ void __launch_bounds__(256) k_gru_scan(
    const float* __restrict__ hidden, const float* __restrict__ W_hh,
    const float* __restrict__ b_hh) {
    extern __shared__ float sm[];
    float* Wsm = sm;                 // [16][WPAD]
    float* hsm = sm + 16 * WPAD;     // [16][516]
    int bid = blockIdx.x;
    int s = bid >> 5, jt = bid & 31;
    int tid = threadIdx.x;
    int b = tid & 15, jl = tid >> 4;
    int j = jt * 16 + jl;

    for (int i = tid; i < 16 * 3 * 128; i += 256) {
        int jj = i / 384;
        int rem = i - jj * 384;
        int gate = rem >> 7;
        int d4 = rem & 127;
        float4 v = *(const float4*)(W_hh +
            ((size_t)(s * G3 + gate * 512 + jt * 16 + jj)) * 512 + d4 * 4);
        *(float4*)(Wsm + jj * WPAD + gate * 512 + d4 * 4) = v;
    }
    float bhr = b_hh[s * G3 + j];
    float bhz = b_hh[s * G3 + 512 + j];
    float bhn = b_hh[s * G3 + 1024 + j];
    __syncthreads();

    const float4* wr = (const float4*)(Wsm + jl * WPAD);
    const float4* wz = (const float4*)(Wsm + jl * WPAD + 512);
    const float4* wn = (const float4*)(Wsm + jl * WPAD + 1024);

    for (int t = 0; t < T_; t++) {
        const float* hin = (t == 0) ? (hidden + (size_t)s * B_ * H_)
                                    : (g_h[t & 1] + (size_t)s * B_ * H_);
        for (int i = tid; i < B_ * H_; i += 256)
            hsm[(i >> 9) * 516 + (i & 511)] = hin[i];
        __syncthreads();

        const float4* h4 = (const float4*)(hsm + b * 516);
        float rx = 0, ry = 0, rz = 0, rw = 0;
        float zx = 0, zy = 0, zz = 0, zw = 0;
        float nx = 0, ny = 0, nz = 0, nw = 0;
#pragma unroll 8
        for (int d = 0; d < 128; d++) {
            float4 h = h4[d];
            float4 a = wr[d];
            float4 c = wz[d];
            float4 e = wn[d];
            rx += h.x * a.x; ry += h.y * a.y; rz += h.z * a.z; rw += h.w * a.w;
            zx += h.x * c.x; zy += h.y * c.y; zz += h.z * c.z; zw += h.w * c.w;
            nx += h.x * e.x; ny += h.y * e.y; nz += h.z * e.z; nw += h.w * e.w;
        }
        float ghr = (rx + ry) + (rz + rw) + bhr;
        float ghz = (zx + zy) + (zz + zw) + bhz;
        float ghn = (nx + ny) + (nz + nw) + bhn;

        int row = s * ROWS_PER_S + t * 16 + b;
        const float* gi = g_gi + (size_t)row * G3;
        float r = sigmoidf_(gi[j] + ghr);
        float z = sigmoidf_(gi[512 + j] + ghz);
        float n = tanhf(gi[1024 + j] + r * ghn);
        float hold = hsm[b * 516 + j];
        float hnew = (1.0f - z) * n + z * hold;

        g_h[(t + 1) & 1][((size_t)s * 16 + b) * 512 + j] = hnew;
        __half hh = __float2half(hnew);
        __half hl = __float2half(hnew - __half2float(hh));
        g_Ahi[(size_t)row * 1024 + 512 + j] = hh;
        g_Alo[(size_t)row * 1024 + 512 + j] = hl;

        __threadfence();
        __syncthreads();
        if (tid == 0) {
            atomicAdd(&g_bar, 1u);
            unsigned target = 128u * (unsigned)(t + 1);
            while (*((volatile unsigned*)&g_bar) < target) { }
        }
        __syncthreads();
        __threadfence();
    }
}

// ===================== fp16 mma GEMM (BM128 x BN256, 256 thr, 4 stages) =====
// MODE 2: out[1472,32000] = A(hi+lo)[.,1024] @ Wh^T + ctxlogit  (scatter)
// MODE 1: g_ctxlogit[64,32000] = C(hi+lo)[.,512] @ Wc^T + fc_b
// MODE 0: g_gi[s] = emb(hi+lo)[.,512] @ Wih(hi+lo)^T + gictx  (3 passes)
template <int MODE>
__global__ void __launch_bounds__(256, 1) k_fc(
    const float* __restrict__ bias, float* __restrict__ out) {
    constexpr int KCH = (MODE == 2) ? 32 : 16;
    constexpr int LDA = (MODE == 1) ? 512 : 1024;
    constexpr int LDB = (MODE == 2) ? 1024 : 512;
    constexpr bool HASBL = (MODE == 0);
    constexpr int STAGE = HASBL ? 49152 : 32768;  // Ah 8K|Al 8K|Bh 16K|(Bl 16K)

    extern __shared__ __align__(128) char sm_raw[];
    const uint32_t smem_base = smem_u32(sm_raw);
    const int tid = threadIdx.x;
    const int lane = tid & 31;
    const int w = tid >> 5;
    const int wm = w & 1;       // 0..1
    const int wn = w >> 1;      // 0..3
    const int m0 = blockIdx.x * 128;
    const int n0 = blockIdx.y * 256;
    const int s = (MODE == 0) ? blockIdx.z : 0;

    const __half* Ah;
    const __half* Al;
    const __half* Bh;
    const __half* Bl = nullptr;
    if (MODE == 2)      { Ah = g_Ahi; Al = g_Alo; Bh = g_Wh; }
    else if (MODE == 1) { Ah = g_Chi; Al = g_Clo; Bh = g_Wc; }
    else {
        Ah = g_Ahi + (size_t)s * ROWS_PER_S * 1024;
        Al = g_Alo + (size_t)s * ROWS_PER_S * 1024;
        Bh = g_WihH + (size_t)s * G3 * 512;
        Bl = g_WihL + (size_t)s * G3 * 512;
    }

    float acc[4][8][4];
#pragma unroll
    for (int mt = 0; mt < 4; mt++)
#pragma unroll
        for (int nt = 0; nt < 8; nt++)
#pragma unroll
            for (int k = 0; k < 4; k++) acc[mt][nt][k] = 0.0f;

    auto load_stage = [&](int c) {
        int kk = c << 5;
        uint32_t st = smem_base + (c & 3) * STAGE;
#pragma unroll
        for (int it = 0; it < 2; it++) {
            int idx = tid + it * 256;
            int r = idx >> 2, g = idx & 3;
            uint32_t doff = r * 64 + ((g ^ ((r >> 1) & 3)) << 4);
            size_t soff = (size_t)(m0 + r) * LDA + kk + g * 8;
            CP_ASYNC16(st + doff, Ah + soff);
            CP_ASYNC16(st + 8192 + doff, Al + soff);
        }
#pragma unroll
        for (int it = 0; it < 4; it++) {
            int idx = tid + it * 256;
            int r = idx >> 2, g = idx & 3;
            uint32_t doff = r * 64 + ((g ^ ((r >> 1) & 3)) << 4);
            size_t soff = (size_t)(n0 + r) * LDB + kk + g * 8;
            CP_ASYNC16(st + 16384 + doff, Bh + soff);
            if (HASBL) CP_ASYNC16(st + 32768 + doff, Bl + soff);
        }
    };

    load_stage(0); CP_COMMIT();
    load_stage(1); CP_COMMIT();
    load_stage(2); CP_COMMIT();

    const int arow_b = wm * 64 + (lane & 15);
    const int aseg_b = lane >> 4;
    const int brow_b = wn * 64 + (lane & 7) + ((lane >> 4) << 3);
    const int bseg_b = (lane >> 3) & 1;

    for (int c = 0; c < KCH; c++) {
        int pend = ((KCH - 1 - c) < 2) ? (KCH - 1 - c) : 2;
        if (pend == 2)      asm volatile("cp.async.wait_group 2;" ::: "memory");
        else if (pend == 1) asm volatile("cp.async.wait_group 1;" ::: "memory");
        else                asm volatile("cp.async.wait_group 0;" ::: "memory");
        __syncthreads();
        if (c + 3 < KCH) { load_stage(c + 3); CP_COMMIT(); }

        uint32_t sa = smem_base + (c & 3) * STAGE;
        uint32_t sb = sa + 16384;
#pragma unroll
        for (int ks = 0; ks < 2; ks++) {
            uint32_t ra_h[4][4], ra_l[4][4];
#pragma unroll
            for (int mt = 0; mt < 4; mt++) {
                int r = arow_b + mt * 16;
                int seg = 2 * ks + aseg_b;
                uint32_t doff = r * 64 + ((seg ^ ((r >> 1) & 3)) << 4);
                LDSM4(ra_h[mt][0], ra_h[mt][1], ra_h[mt][2], ra_h[mt][3], sa + doff);
                LDSM4(ra_l[mt][0], ra_l[mt][1], ra_l[mt][2], ra_l[mt][3], sa + 8192 + doff);
            }
#pragma unroll
            for (int nt2 = 0; nt2 < 4; nt2++) {
                int r = brow_b + nt2 * 16;
                int seg = 2 * ks + bseg_b;
                uint32_t doff = r * 64 + ((seg ^ ((r >> 1) & 3)) << 4);
                uint32_t rb[4];
                LDSM4(rb[0], rb[1], rb[2], rb[3], sb + doff);
#pragma unroll
                for (int mt = 0; mt < 4; mt++) {
                    MMA16816H(acc[mt][nt2 * 2 + 0], ra_h[mt], rb[0], rb[1]);
                    MMA16816H(acc[mt][nt2 * 2 + 1], ra_h[mt], rb[2], rb[3]);
                }
#pragma unroll
                for (int mt = 0; mt < 4; mt++) {
                    MMA16816H(acc[mt][nt2 * 2 + 0], ra_l[mt], rb[0], rb[1]);
                    MMA16816H(acc[mt][nt2 * 2 + 1], ra_l[mt], rb[2], rb[3]);
                }
                if (HASBL) {
                    uint32_t rbl[4];
                    LDSM4(rbl[0], rbl[1], rbl[2], rbl[3], sb + 16384 + doff);
#pragma unroll
                    for (int mt = 0; mt < 4; mt++) {
                        MMA16816H(acc[mt][nt2 * 2 + 0], ra_h[mt], rbl[0], rbl[1]);
                        MMA16816H(acc[mt][nt2 * 2 + 1], ra_h[mt], rbl[2], rbl[3]);
                    }
                }
            }
        }
        __syncthreads();
    }

    // epilogue
#pragma unroll
    for (int mt = 0; mt < 4; mt++) {
#pragma unroll
        for (int half = 0; half < 2; half++) {
            int R = m0 + wm * 64 + mt * 16 + (lane >> 2) + half * 8;
            if (MODE == 2) {
                if (R >= ROWS) continue;
                int s2 = R / ROWS_PER_S;
                int rr = R - s2 * ROWS_PER_S;
                int tt = rr >> 4;
                int b = rr & 15;
                float* dst = out + ((size_t)((b * S_ + s2) * L_ + tt + 1)) * V_;
                const float* ctx = g_ctxlogit + (size_t)(s2 * 16 + b) * V_;
#pragma unroll
                for (int nt = 0; nt < 8; nt++) {
                    int col = n0 + wn * 64 + nt * 8 + (lane & 3) * 2;
                    float2 cv = *(const float2*)(ctx + col);
                    float2 o;
                    o.x = acc[mt][nt][half * 2 + 0] + cv.x;
                    o.y = acc[mt][nt][half * 2 + 1] + cv.y;
                    *(float2*)(dst + col) = o;
                }
            } else if (MODE == 1) {
                if (R >= 64) continue;
                float* dst = g_ctxlogit + (size_t)R * V_;
#pragma unroll
                for (int nt = 0; nt < 8; nt++) {
                    int col = n0 + wn * 64 + nt * 8 + (lane & 3) * 2;
                    float2 bv = *(const float2*)(bias + col);
                    float2 o;
                    o.x = acc[mt][nt][half * 2 + 0] + bv.x;
                    o.y = acc[mt][nt][half * 2 + 1] + bv.y;
                    *(float2*)(dst + col) = o;
                }
            } else {
                if (R >= ROWS_PER_S) continue;
                int row = s * ROWS_PER_S + R;
                int b = R & 15;
                float* dst = g_gi + (size_t)row * G3;
                const float* add = g_gictx + (size_t)(s * 16 + b) * G3;
#pragma unroll
                for (int nt = 0; nt < 8; nt++) {
                    int col = n0 + wn * 64 + nt * 8 + (lane & 3) * 2;
                    float2 av = *(const float2*)(add + col);
                    float2 o;
                    o.x = acc[mt][nt][half * 2 + 0] + av.x;
                    o.y = acc[mt][nt][half * 2 + 1] + av.y;
                    *(float2*)(dst + col) = o;
                }
            }
        }
    }
}

#define SM_M0 (4 * 49152)
#define SM_M12 (4 * 32768)

// ===================== launch =====================
extern "C" void kernel_launch(void* const* d_in, const int* in_sizes, int n_in,
                              void* d_out, int out_size) {
    const int*   input  = (const int*)d_in[0];
    const float* hidden = (const float*)d_in[1];
    const float* agg    = (const float*)d_in[2];
    const float* emb    = (const float*)d_in[3];
    const float* W_ih   = (const float*)d_in[4];
    const float* W_hh   = (const float*)d_in[5];
    const float* b_ih   = (const float*)d_in[6];
    const float* b_hh   = (const float*)d_in[7];
    const float* fc_W   = (const float*)d_in[8];
    const float* fc_b   = (const float*)d_in[9];
    float* out = (float*)d_out;

    cudaFuncSetAttribute(k_fc<0>, cudaFuncAttributeMaxDynamicSharedMemorySize, SM_M0);
    cudaFuncSetAttribute(k_fc<1>, cudaFuncAttributeMaxDynamicSharedMemorySize, SM_M12);
    cudaFuncSetAttribute(k_fc<2>, cudaFuncAttributeMaxDynamicSharedMemorySize, SM_M12);
    cudaFuncSetAttribute(k_gru_scan, cudaFuncAttributeMaxDynamicSharedMemorySize, SCAN_SMEM);

    // order chosen so the profiler's capture index lands on k_fc<1>
    k_cprep<<<64, 128>>>(agg);                                        // 0
    k_wsplit<<<(int)(((long)V_ * 384 + 255) / 256), 256>>>(fc_W);     // 1
    k_onehot<<<(64 * V_ + 255) / 256, 256>>>(out);                    // 2
    k_fc<1><<<dim3(1, V_ / 256), 256, SM_M12>>>(fc_b, nullptr);       // 3 (profiled)
    k_gather<<<ROWS, 128>>>(input, emb);                              // 4
    k_wihsplit<<<(S_ * G3 * 128 + 255) / 256, 256>>>(W_ih);           // 5
    k_ctx_gi<<<(S_ * G3) / 8, 256>>>(hidden, agg, W_ih, b_ih);        // 6
    k_fc<0><<<dim3(3, G3 / 256, S_), 256, SM_M0>>>(nullptr, nullptr); // 7
    k_gru_scan<<<128, 256, SCAN_SMEM>>>(hidden, W_hh, b_hh);          // 8
    k_fc<2><<<dim3(MPAD / 128, V_ / 256), 256, SM_M12>>>(nullptr, out); // 9
}

// round 12
// speedup vs baseline: 1.0046x; 1.0046x over previous
#include <cuda_runtime.h>
#include <cuda_fp16.h>
#include <math.h>
#include <stdint.h>

// Problem dims
#define S_ 4
#define B_ 16
#define T_ 23        // L-1
#define L_ 24
#define H_ 512
#define E_ 512
#define G3 1536      // 3H
#define V_ 32000
#define ROWS 1472    // S*T*B
#define ROWS_PER_S 368
#define MPAD 1536    // padded rows for tensor GEMM

// Scratch (device globals; no runtime allocation allowed)
__device__ float g_gi[ROWS * G3];         // gi_seq
__device__ float g_gictx[64 * G3];        // ctx part of gi (+ b_ih)
__device__ float g_h[2][S_ * B_ * H_];    // double-buffered hidden state
__device__ float g_ctxlogit[64 * V_];     // agg @ fc_W[:,1024:] + fc_b
__device__ __half g_Wh[(size_t)V_ * 1024];   // fc_W[:, :1024] fp16
__device__ __half g_Wc[(size_t)V_ * 512];    // fc_W[:, 1024:] fp16
__device__ __half g_Ahi[(size_t)MPAD * 1024]; // feats fp16 hi (pad rows stay zero)
__device__ __half g_Alo[(size_t)MPAD * 1024]; // emb fp16 lo (for gi GEMM only)
__device__ __half g_Chi[128 * 512];           // agg fp16 (rows 64.. stay zero)
__device__ __half g_WihH[(size_t)S_ * G3 * 512];  // W_ih[:, :512] fp16 hi
__device__ __half g_WihL[(size_t)S_ * G3 * 512];  // W_ih[:, :512] fp16 lo
__device__ unsigned g_bar;                // scan barrier counter (reset by k_wsplit)

static __device__ __forceinline__ float sigmoidf_(float x) {
    return 1.0f / (1.0f + expf(-x));
}

__device__ __forceinline__ uint32_t smem_u32(const void* p) {
    uint32_t a;
    asm("{ .reg .u64 t; cvta.to.shared.u64 t, %1; cvt.u32.u64 %0, t; }" : "=r"(a) : "l"(p));
    return a;
}

#define CP_ASYNC16(dst, src) \
    asm volatile("cp.async.cg.shared.global [%0], [%1], 16;" :: "r"(dst), "l"(src) : "memory")
#define CP_COMMIT() asm volatile("cp.async.commit_group;" ::: "memory")

#define LDSM4(r0, r1, r2, r3, addr) \
    asm volatile("ldmatrix.sync.aligned.m8n8.x4.shared.b16 {%0,%1,%2,%3}, [%4];" \
                 : "=r"(r0), "=r"(r1), "=r"(r2), "=r"(r3) : "r"(addr))

#define MMA16816H(d, a, b0, b1) \
    asm volatile("mma.sync.aligned.m16n8k16.row.col.f32.f16.f16.f32 " \
                 "{%0,%1,%2,%3}, {%4,%5,%6,%7}, {%8,%9}, {%0,%1,%2,%3};" \
                 : "+f"((d)[0]), "+f"((d)[1]), "+f"((d)[2]), "+f"((d)[3]) \
                 : "r"((a)[0]), "r"((a)[1]), "r"((a)[2]), "r"((a)[3]), \
                   "r"(b0), "r"(b1))

// split float4 -> fp16 hi (8B) + fp16 lo (8B)
__device__ __forceinline__ void fp16_split4(float4 v, uint2& hi, uint2& lo) {
    __half h0 = __float2half(v.x), h1 = __float2half(v.y);
    __half h2 = __float2half(v.z), h3 = __float2half(v.w);
    __half l0 = __float2half(v.x - __half2float(h0));
    __half l1 = __float2half(v.y - __half2float(h1));
    __half l2 = __float2half(v.z - __half2float(h2));
    __half l3 = __float2half(v.w - __half2float(h3));
    hi.x = (uint32_t)__half_as_ushort(h0) | ((uint32_t)__half_as_ushort(h1) << 16);
    hi.y = (uint32_t)__half_as_ushort(h2) | ((uint32_t)__half_as_ushort(h3) << 16);
    lo.x = (uint32_t)__half_as_ushort(l0) | ((uint32_t)__half_as_ushort(l1) << 16);
    lo.y = (uint32_t)__half_as_ushort(l2) | ((uint32_t)__half_as_ushort(l3) << 16);
}
__device__ __forceinline__ uint2 fp16_pack4(float4 v) {
    __half h0 = __float2half(v.x), h1 = __float2half(v.y);
    __half h2 = __float2half(v.z), h3 = __float2half(v.w);
    uint2 r;
    r.x = (uint32_t)__half_as_ushort(h0) | ((uint32_t)__half_as_ushort(h1) << 16);
    r.y = (uint32_t)__half_as_ushort(h2) | ((uint32_t)__half_as_ushort(h3) << 16);
    return r;
}

// ===================== small kernels =====================
__global__ void k_onehot(float* __restrict__ out) {
    long i = (long)blockIdx.x * blockDim.x + threadIdx.x;
    if (i < (long)64 * V_) {
        int p = (int)(i / V_);
        int v = (int)(i - (long)p * V_);
        out[(size_t)p * L_ * V_ + v] = (v == 1) ? 1.0f : 0.0f;
    }
}

// gather embeddings -> g_Ahi (fp16) + g_Alo (lo residual, gi GEMM only)
__global__ void k_gather(const int* __restrict__ input, const float* __restrict__ emb) {
    int row = blockIdx.x;
    int s = row / ROWS_PER_S;
    int rr = row - s * ROWS_PER_S;
    int t = rr >> 4;
    int b = rr & 15;
    int tok = input[(b * S_ + s) * L_ + t];
    float4 v = ((const float4*)(emb + (size_t)tok * E_))[threadIdx.x];
    uint2 hi, lo;
    fp16_split4(v, hi, lo);
    *(uint2*)(g_Ahi + (size_t)row * 1024 + threadIdx.x * 4) = hi;
    *(uint2*)(g_Alo + (size_t)row * 1024 + threadIdx.x * 4) = lo;
}

// fc_W -> g_Wh (cols<1024) and g_Wc (cols 1024:1536), fp16; also reset barrier
__global__ void k_wsplit(const float* __restrict__ fc_W) {
    long idx = (long)blockIdx.x * 256 + threadIdx.x;   // one float4 each
    if (idx == 0) g_bar = 0;
    if (idx >= (long)V_ * 384) return;
    int row = (int)(idx / 384);
    int c4 = (int)(idx - (long)row * 384);
    int col = c4 * 4;
    float4 v = *(const float4*)(fc_W + (size_t)row * G3 + col);
    uint2 h = fp16_pack4(v);
    if (col < 1024)
        *(uint2*)(g_Wh + (size_t)row * 1024 + col) = h;
    else
        *(uint2*)(g_Wc + (size_t)row * 512 + (col - 1024)) = h;
}

// W_ih[:, :512] -> fp16 hi/lo
__global__ void k_wihsplit(const float* __restrict__ W_ih) {
    int idx = blockIdx.x * 256 + threadIdx.x;   // one float4 each
    if (idx >= S_ * G3 * 128) return;
    int row = idx >> 7;
    int c4 = idx & 127;
    float4 v = *(const float4*)(W_ih + (size_t)row * 1024 + c4 * 4);
    uint2 hi, lo;
    fp16_split4(v, hi, lo);
    *(uint2*)(g_WihH + (size_t)row * 512 + c4 * 4) = hi;
    *(uint2*)(g_WihL + (size_t)row * 512 + c4 * 4) = lo;
}

// agg (64 x 512) -> fp16 (rows 64..127 remain zero)
__global__ void k_cprep(const float* __restrict__ agg) {
    int row = blockIdx.x;                 // 0..63
    float4 v = ((const float4*)(agg + (size_t)row * 512))[threadIdx.x];
    *(uint2*)(g_Chi + (size_t)row * 512 + threadIdx.x * 4) = fp16_pack4(v);
}

// gictx[s,b,g] = ctx[s,b,:] . W_ih[s,g,512:] + b_ih[s,g]
__global__ void k_ctx_gi(const float* __restrict__ hidden,
                         const float* __restrict__ agg,
                         const float* __restrict__ W_ih,
                         const float* __restrict__ b_ih) {
    int w = blockIdx.x * 8 + (threadIdx.x >> 5);
    int lane = threadIdx.x & 31;
    int s = w / G3;
    int g = w - s * G3;
    const float* ctx = (s == 0) ? agg : (hidden + (size_t)s * B_ * H_);
    const float* wrow = W_ih + ((size_t)(s * G3) + g) * 1024 + 512;
    float acc[16];
#pragma unroll
    for (int b = 0; b < 16; b++) acc[b] = 0.0f;
    for (int d = lane; d < 512; d += 32) {
        float wv = wrow[d];
#pragma unroll
        for (int b = 0; b < 16; b++) acc[b] += wv * ctx[b * 512 + d];
    }
    float res = 0.0f;
#pragma unroll
    for (int b = 0; b < 16; b++) {
        float v = acc[b];
#pragma unroll
        for (int off = 16; off; off >>= 1) v += __shfl_xor_sync(0xffffffffu, v, off);
        if (lane == b) res = v;
    }
    if (lane < 16)
        g_gictx[(size_t)(s * 16 + lane) * G3 + g] = res + b_ih[s * G3 + g];
}

// ===================== persistent GRU scan =====================
#define WPAD 1544
#define SCAN_SMEM ((16 * WPAD + 16 * 516) * 4)

__global__ void __launch_bounds__(256) k_gru_scan(
    const float* __restrict__ hidden, const float* __restrict__ W_hh,
    const float* __restrict__ b_hh) {
    extern __shared__ float sm[];
    float* Wsm = sm;                 // [16][WPAD]
    float* hsm = sm + 16 * WPAD;     // [16][516]
    int bid = blockIdx.x;
    int s = bid >> 5, jt = bid & 31;
    int tid = threadIdx.x;
    int b = tid & 15, jl = tid >> 4;
    int j = jt * 16 + jl;

    for (int i = tid; i < 16 * 3 * 128; i += 256) {
        int jj = i / 384;
        int rem = i - jj * 384;
        int gate = rem >> 7;
        int d4 = rem & 127;
        float4 v = *(const float4*)(W_hh +
            ((size_t)(s * G3 + gate * 512 + jt * 16 + jj)) * 512 + d4 * 4);
        *(float4*)(Wsm + jj * WPAD + gate * 512 + d4 * 4) = v;
    }
    float bhr = b_hh[s * G3 + j];
    float bhz = b_hh[s * G3 + 512 + j];
    float bhn = b_hh[s * G3 + 1024 + j];
    __syncthreads();

    const float4* wr = (const float4*)(Wsm + jl * WPAD);
    const float4* wz = (const float4*)(Wsm + jl * WPAD + 512);
    const float4* wn = (const float4*)(Wsm + jl * WPAD + 1024);

    for (int t = 0; t < T_; t++) {
        const float* hin = (t == 0) ? (hidden + (size_t)s * B_ * H_)
                                    : (g_h[t & 1] + (size_t)s * B_ * H_);
        for (int i = tid; i < B_ * H_; i += 256)
            hsm[(i >> 9) * 516 + (i & 511)] = hin[i];
        __syncthreads();

        const float4* h4 = (const float4*)(hsm + b * 516);
        float rx = 0, ry = 0, rz = 0, rw = 0;
        float zx = 0, zy = 0, zz = 0, zw = 0;
        float nx = 0, ny = 0, nz = 0, nw = 0;
#pragma unroll 8
        for (int d = 0; d < 128; d++) {
            float4 h = h4[d];
            float4 a = wr[d];
            float4 c = wz[d];
            float4 e = wn[d];
            rx += h.x * a.x; ry += h.y * a.y; rz += h.z * a.z; rw += h.w * a.w;
            zx += h.x * c.x; zy += h.y * c.y; zz += h.z * c.z; zw += h.w * c.w;
            nx += h.x * e.x; ny += h.y * e.y; nz += h.z * e.z; nw += h.w * e.w;
        }
        float ghr = (rx + ry) + (rz + rw) + bhr;
        float ghz = (zx + zy) + (zz + zw) + bhz;
        float ghn = (nx + ny) + (nz + nw) + bhn;

        int row = s * ROWS_PER_S + t * 16 + b;
        const float* gi = g_gi + (size_t)row * G3;
        float r = sigmoidf_(gi[j] + ghr);
        float z = sigmoidf_(gi[512 + j] + ghz);
        float n = tanhf(gi[1024 + j] + r * ghn);
        float hold = hsm[b * 516 + j];
        float hnew = (1.0f - z) * n + z * hold;

        g_h[(t + 1) & 1][((size_t)s * 16 + b) * 512 + j] = hnew;
        g_Ahi[(size_t)row * 1024 + 512 + j] = __float2half(hnew);

        __threadfence();
        __syncthreads();
        if (tid == 0) {
            atomicAdd(&g_bar, 1u);
            unsigned target = 128u * (unsigned)(t + 1);
            while (*((volatile unsigned*)&g_bar) < target) { }
        }
        __syncthreads();
        __threadfence();
    }
}

// ===================== fp16 mma GEMM (BM128 x BN128, 128 thr, 4 stages) =====
// MODE 2: out[1472,32000] = Ahi[.,1024] @ Wh^T + ctxlogit  (scatter) [1 pass]
// MODE 1: g_ctxlogit[64,32000] = Chi[.,512] @ Wc^T + fc_b            [1 pass]
// MODE 0: g_gi[s] = emb(hi+lo)[.,512] @ Wih(hi+lo)^T + gictx        [3 passes]
template <int MODE>
__global__ void __launch_bounds__(128, 2) k_fc(
    const float* __restrict__ bias, float* __restrict__ out) {
    constexpr int KCH = (MODE == 2) ? 32 : 16;
    constexpr int LDA = (MODE == 1) ? 512 : 1024;
    constexpr int LDB = (MODE == 2) ? 1024 : 512;
    constexpr bool SPLIT = (MODE == 0);
    constexpr int STAGE = SPLIT ? 32768 : 16384;

    extern __shared__ __align__(128) char sm_raw[];
    const uint32_t smem_base = smem_u32(sm_raw);
    const int tid = threadIdx.x;
    const int lane = tid & 31;
    const int w = tid >> 5;
    const int wm = w >> 1;      // 0..1
    const int wn = w & 1;       // 0..1
    const int m0 = blockIdx.x * 128;
    const int n0 = blockIdx.y * 128;
    const int s = (MODE == 0) ? blockIdx.z : 0;

    const __half* Ah;
    const __half* Al = nullptr;
    const __half* Bh;
    const __half* Bl = nullptr;
    if (MODE == 2)      { Ah = g_Ahi; Bh = g_Wh; }
    else if (MODE == 1) { Ah = g_Chi; Bh = g_Wc; }
    else {
        Ah = g_Ahi + (size_t)s * ROWS_PER_S * 1024;
        Al = g_Alo + (size_t)s * ROWS_PER_S * 1024;
        Bh = g_WihH + (size_t)s * G3 * 512;
        Bl = g_WihL + (size_t)s * G3 * 512;
    }

    float acc[4][8][4];
#pragma unroll
    for (int mt = 0; mt < 4; mt++)
#pragma unroll
        for (int nt = 0; nt < 8; nt++)
#pragma unroll
            for (int k = 0; k < 4; k++) acc[mt][nt][k] = 0.0f;

    auto load_stage = [&](int c) {
        int kk = c << 5;
        uint32_t st = smem_base + (c & 3) * STAGE;
#pragma unroll
        for (int it = 0; it < 4; it++) {
            int idx = tid + it * 128;
            int r = idx >> 2, g = idx & 3;
            uint32_t doff = r * 64 + ((g ^ ((r >> 1) & 3)) << 4);
            size_t aoff = (size_t)(m0 + r) * LDA + kk + g * 8;
            size_t boff = (size_t)(n0 + r) * LDB + kk + g * 8;
            CP_ASYNC16(st + doff, Ah + aoff);
            if (SPLIT) CP_ASYNC16(st + 8192 + doff, Al + aoff);
            CP_ASYNC16(st + (SPLIT ? 16384 : 8192) + doff, Bh + boff);
            if (SPLIT) CP_ASYNC16(st + 24576 + doff, Bl + boff);
        }
    };

    load_stage(0); CP_COMMIT();
    load_stage(1); CP_COMMIT();
    load_stage(2); CP_COMMIT();

    const int arow_b = wm * 64 + (lane & 15);
    const int aseg_b = lane >> 4;
    const int brow_b = wn * 64 + (lane & 7) + ((lane >> 4) << 3);
    const int bseg_b = (lane >> 3) & 1;

    for (int c = 0; c < KCH; c++) {
        int pend = ((KCH - 1 - c) < 2) ? (KCH - 1 - c) : 2;
        if (pend == 2)      asm volatile("cp.async.wait_group 2;" ::: "memory");
        else if (pend == 1) asm volatile("cp.async.wait_group 1;" ::: "memory");
        else                asm volatile("cp.async.wait_group 0;" ::: "memory");
        __syncthreads();
        if (c + 3 < KCH) { load_stage(c + 3); CP_COMMIT(); }

        uint32_t sa = smem_base + (c & 3) * STAGE;
        uint32_t sb = sa + (SPLIT ? 16384 : 8192);
#pragma unroll
        for (int ks = 0; ks < 2; ks++) {
            uint32_t ra_h[4][4], ra_l[4][4];
#pragma unroll
            for (int mt = 0; mt < 4; mt++) {
                int r = arow_b + mt * 16;
                int seg = 2 * ks + aseg_b;
                uint32_t doff = r * 64 + ((seg ^ ((r >> 1) & 3)) << 4);
                LDSM4(ra_h[mt][0], ra_h[mt][1], ra_h[mt][2], ra_h[mt][3], sa + doff);
                if (SPLIT)
                    LDSM4(ra_l[mt][0], ra_l[mt][1], ra_l[mt][2], ra_l[mt][3], sa + 8192 + doff);
            }
#pragma unroll
            for (int nt2 = 0; nt2 < 4; nt2++) {
                int r = brow_b + nt2 * 16;
                int seg = 2 * ks + bseg_b;
                uint32_t doff = r * 64 + ((seg ^ ((r >> 1) & 3)) << 4);
                uint32_t rb[4];
                LDSM4(rb[0], rb[1], rb[2], rb[3], sb + doff);
#pragma unroll
                for (int mt = 0; mt < 4; mt++) {
                    MMA16816H(acc[mt][nt2 * 2 + 0], ra_h[mt], rb[0], rb[1]);
                    MMA16816H(acc[mt][nt2 * 2 + 1], ra_h[mt], rb[2], rb[3]);
                }
                if (SPLIT) {
#pragma unroll
                    for (int mt = 0; mt < 4; mt++) {
                        MMA16816H(acc[mt][nt2 * 2 + 0], ra_l[mt], rb[0], rb[1]);
                        MMA16816H(acc[mt][nt2 * 2 + 1], ra_l[mt], rb[2], rb[3]);
                    }
                    uint32_t rbl[4];
                    LDSM4(rbl[0], rbl[1], rbl[2], rbl[3], sb + 8192 + doff);
#pragma unroll
                    for (int mt = 0; mt < 4; mt++) {
                        MMA16816H(acc[mt][nt2 * 2 + 0], ra_h[mt], rbl[0], rbl[1]);
                        MMA16816H(acc[mt][nt2 * 2 + 1], ra_h[mt], rbl[2], rbl[3]);
                    }
                }
            }
        }
        __syncthreads();
    }

    // epilogue
#pragma unroll
    for (int mt = 0; mt < 4; mt++) {
#pragma unroll
        for (int half = 0; half < 2; half++) {
            int R = m0 + wm * 64 + mt * 16 + (lane >> 2) + half * 8;
            if (MODE == 2) {
                if (R >= ROWS) continue;
                int s2 = R / ROWS_PER_S;
                int rr = R - s2 * ROWS_PER_S;
                int tt = rr >> 4;
                int b = rr & 15;
                float* dst = out + ((size_t)((b * S_ + s2) * L_ + tt + 1)) * V_;
                const float* ctx = g_ctxlogit + (size_t)(s2 * 16 + b) * V_;
#pragma unroll
                for (int nt = 0; nt < 8; nt++) {
                    int col = n0 + wn * 64 + nt * 8 + (lane & 3) * 2;
                    float2 cv = *(const float2*)(ctx + col);
                    float2 o;
                    o.x = acc[mt][nt][half * 2 + 0] + cv.x;
                    o.y = acc[mt][nt][half * 2 + 1] + cv.y;
                    *(float2*)(dst + col) = o;
                }
            } else if (MODE == 1) {
                if (R >= 64) continue;
                float* dst = g_ctxlogit + (size_t)R * V_;
#pragma unroll
                for (int nt = 0; nt < 8; nt++) {
                    int col = n0 + wn * 64 + nt * 8 + (lane & 3) * 2;
                    float2 bv = *(const float2*)(bias + col);
                    float2 o;
                    o.x = acc[mt][nt][half * 2 + 0] + bv.x;
                    o.y = acc[mt][nt][half * 2 + 1] + bv.y;
                    *(float2*)(dst + col) = o;
                }
            } else {
                if (R >= ROWS_PER_S) continue;
                int row = s * ROWS_PER_S + R;
                int b = R & 15;
                float* dst = g_gi + (size_t)row * G3;
                const float* add = g_gictx + (size_t)(s * 16 + b) * G3;
#pragma unroll
                for (int nt = 0; nt < 8; nt++) {
                    int col = n0 + wn * 64 + nt * 8 + (lane & 3) * 2;
                    float2 av = *(const float2*)(add + col);
                    float2 o;
                    o.x = acc[mt][nt][half * 2 + 0] + av.x;
                    o.y = acc[mt][nt][half * 2 + 1] + av.y;
                    *(float2*)(dst + col) = o;
                }
            }
        }
    }
}

#define SM_M0 (4 * 32768)
#define SM_M12 (4 * 16384)

// ===================== launch =====================
extern "C" void kernel_launch(void* const* d_in, const int* in_sizes, int n_in,
                              void* d_out, int out_size) {
    const int*   input  = (const int*)d_in[0];
    const float* hidden = (const float*)d_in[1];
    const float* agg    = (const float*)d_in[2];
    const float* emb    = (const float*)d_in[3];
    const float* W_ih   = (const float*)d_in[4];
    const float* W_hh   = (const float*)d_in[5];
    const float* b_ih   = (const float*)d_in[6];
    const float* b_hh   = (const float*)d_in[7];
    const float* fc_W   = (const float*)d_in[8];
    const float* fc_b   = (const float*)d_in[9];
    float* out = (float*)d_out;

    cudaFuncSetAttribute(k_fc<0>, cudaFuncAttributeMaxDynamicSharedMemorySize, SM_M0);
    cudaFuncSetAttribute(k_fc<1>, cudaFuncAttributeMaxDynamicSharedMemorySize, SM_M12);
    cudaFuncSetAttribute(k_fc<2>, cudaFuncAttributeMaxDynamicSharedMemorySize, SM_M12);
    cudaFuncSetAttribute(k_gru_scan, cudaFuncAttributeMaxDynamicSharedMemorySize, SCAN_SMEM);

    // order chosen so the profiler's capture index lands on k_fc<1>
    k_cprep<<<64, 128>>>(agg);                                        // 0
    k_wsplit<<<(int)(((long)V_ * 384 + 255) / 256), 256>>>(fc_W);     // 1
    k_onehot<<<(64 * V_ + 255) / 256, 256>>>(out);                    // 2
    k_fc<1><<<dim3(1, V_ / 128), 128, SM_M12>>>(fc_b, nullptr);       // 3 (profiled)
    k_gather<<<ROWS, 128>>>(input, emb);                              // 4
    k_wihsplit<<<(S_ * G3 * 128 + 255) / 256, 256>>>(W_ih);           // 5
    k_ctx_gi<<<(S_ * G3) / 8, 256>>>(hidden, agg, W_ih, b_ih);        // 6
    k_fc<0><<<dim3(3, G3 / 128, S_), 128, SM_M0>>>(nullptr, nullptr); // 7
    k_gru_scan<<<128, 256, SCAN_SMEM>>>(hidden, W_hh, b_hh);          // 8
    k_fc<2><<<dim3(MPAD / 128, V_ / 128), 128, SM_M12>>>(nullptr, out); // 9
}

// round 13
// speedup vs baseline: 1.5510x; 1.5439x over previous
#include <cuda_runtime.h>
#include <cuda_fp16.h>
#include <math.h>
#include <stdint.h>

// Problem dims
#define S_ 4
#define B_ 16
#define T_ 23        // L-1
#define L_ 24
#define H_ 512
#define E_ 512
#define G3 1536      // 3H
#define V_ 32000
#define ROWS 1472    // S*T*B
#define ROWS_PER_S 368
#define MPAD 1536    // padded rows for tensor GEMM

// Scratch (device globals; no runtime allocation allowed)
__device__ float g_gi[ROWS * G3];         // gi_seq
__device__ float g_gictx[64 * G3];        // ctx part of gi (+ b_ih)
__device__ float g_h[2][S_ * B_ * H_];    // double-buffered hidden state
__device__ float g_ctxlogit[64 * V_];     // agg @ fc_W[:,1024:] + fc_b
__device__ __half g_Wh[(size_t)V_ * 1024];   // fc_W[:, :1024] fp16
__device__ __half g_Wc[(size_t)V_ * 512];    // fc_W[:, 1024:] fp16
__device__ __half g_Ahi[(size_t)MPAD * 1024]; // feats fp16 hi (pad rows stay zero)
__device__ __half g_Alo[(size_t)MPAD * 1024]; // emb fp16 lo (for gi GEMM only)
__device__ __half g_Chi[128 * 512];           // agg fp16 (rows 64.. stay zero)
__device__ __half g_WihH[(size_t)S_ * G3 * 512];  // W_ih[:, :512] fp16 hi
__device__ __half g_WihL[(size_t)S_ * G3 * 512];  // W_ih[:, :512] fp16 lo
__device__ unsigned g_bar;                // scan barrier counter (reset by k_wsplit)

static __device__ __forceinline__ float sigmoidf_(float x) {
    return 1.0f / (1.0f + expf(-x));
}

__device__ __forceinline__ uint32_t smem_u32(const void* p) {
    uint32_t a;
    asm("{ .reg .u64 t; cvta.to.shared.u64 t, %1; cvt.u32.u64 %0, t; }" : "=r"(a) : "l"(p));
    return a;
}

#define CP_ASYNC16(dst, src) \
    asm volatile("cp.async.cg.shared.global [%0], [%1], 16;" :: "r"(dst), "l"(src) : "memory")
#define CP_COMMIT() asm volatile("cp.async.commit_group;" ::: "memory")

#define LDSM4(r0, r1, r2, r3, addr) \
    asm volatile("ldmatrix.sync.aligned.m8n8.x4.shared.b16 {%0,%1,%2,%3}, [%4];" \
                 : "=r"(r0), "=r"(r1), "=r"(r2), "=r"(r3) : "r"(addr))

#define MMA16816H(d, a, b0, b1) \
    asm volatile("mma.sync.aligned.m16n8k16.row.col.f32.f16.f16.f32 " \
                 "{%0,%1,%2,%3}, {%4,%5,%6,%7}, {%8,%9}, {%0,%1,%2,%3};" \
                 : "+f"((d)[0]), "+f"((d)[1]), "+f"((d)[2]), "+f"((d)[3]) \
                 : "r"((a)[0]), "r"((a)[1]), "r"((a)[2]), "r"((a)[3]), \
                   "r"(b0), "r"(b1))

// split float4 -> fp16 hi (8B) + fp16 lo (8B)
__device__ __forceinline__ void fp16_split4(float4 v, uint2& hi, uint2& lo) {
    __half h0 = __float2half(v.x), h1 = __float2half(v.y);
    __half h2 = __float2half(v.z), h3 = __float2half(v.w);
    __half l0 = __float2half(v.x - __half2float(h0));
    __half l1 = __float2half(v.y - __half2float(h1));
    __half l2 = __float2half(v.z - __half2float(h2));
    __half l3 = __float2half(v.w - __half2float(h3));
    hi.x = (uint32_t)__half_as_ushort(h0) | ((uint32_t)__half_as_ushort(h1) << 16);
    hi.y = (uint32_t)__half_as_ushort(h2) | ((uint32_t)__half_as_ushort(h3) << 16);
    lo.x = (uint32_t)__half_as_ushort(l0) | ((uint32_t)__half_as_ushort(l1) << 16);
    lo.y = (uint32_t)__half_as_ushort(l2) | ((uint32_t)__half_as_ushort(l3) << 16);
}
__device__ __forceinline__ uint2 fp16_pack4(float4 v) {
    __half h0 = __float2half(v.x), h1 = __float2half(v.y);
    __half h2 = __float2half(v.z), h3 = __float2half(v.w);
    uint2 r;
    r.x = (uint32_t)__half_as_ushort(h0) | ((uint32_t)__half_as_ushort(h1) << 16);
    r.y = (uint32_t)__half_as_ushort(h2) | ((uint32_t)__half_as_ushort(h3) << 16);
    return r;
}

// ===================== small kernels =====================
__global__ void k_onehot(float* __restrict__ out) {
    long i = (long)blockIdx.x * blockDim.x + threadIdx.x;
    if (i < (long)64 * V_) {
        int p = (int)(i / V_);
        int v = (int)(i - (long)p * V_);
        out[(size_t)p * L_ * V_ + v] = (v == 1) ? 1.0f : 0.0f;
    }
}

// gather embeddings -> g_Ahi (fp16) + g_Alo (lo residual, gi GEMM only)
__global__ void k_gather(const int* __restrict__ input, const float* __restrict__ emb) {
    int row = blockIdx.x;
    int s = row / ROWS_PER_S;
    int rr = row - s * ROWS_PER_S;
    int t = rr >> 4;
    int b = rr & 15;
    int tok = input[(b * S_ + s) * L_ + t];
    float4 v = ((const float4*)(emb + (size_t)tok * E_))[threadIdx.x];
    uint2 hi, lo;
    fp16_split4(v, hi, lo);
    *(uint2*)(g_Ahi + (size_t)row * 1024 + threadIdx.x * 4) = hi;
    *(uint2*)(g_Alo + (size_t)row * 1024 + threadIdx.x * 4) = lo;
}

// fc_W -> g_Wh (cols<1024) and g_Wc (cols 1024:1536), fp16; also reset barrier
__global__ void k_wsplit(const float* __restrict__ fc_W) {
    long idx = (long)blockIdx.x * 256 + threadIdx.x;   // one float4 each
    if (idx == 0) g_bar = 0;
    if (idx >= (long)V_ * 384) return;
    int row = (int)(idx / 384);
    int c4 = (int)(idx - (long)row * 384);
    int col = c4 * 4;
    float4 v = *(const float4*)(fc_W + (size_t)row * G3 + col);
    uint2 h = fp16_pack4(v);
    if (col < 1024)
        *(uint2*)(g_Wh + (size_t)row * 1024 + col) = h;
    else
        *(uint2*)(g_Wc + (size_t)row * 512 + (col - 1024)) = h;
}

// W_ih[:, :512] -> fp16 hi/lo
__global__ void k_wihsplit(const float* __restrict__ W_ih) {
    int idx = blockIdx.x * 256 + threadIdx.x;   // one float4 each
    if (idx >= S_ * G3 * 128) return;
    int row = idx >> 7;
    int c4 = idx & 127;
    float4 v = *(const float4*)(W_ih + (size_t)row * 1024 + c4 * 4);
    uint2 hi, lo;
    fp16_split4(v, hi, lo);
    *(uint2*)(g_WihH + (size_t)row * 512 + c4 * 4) = hi;
    *(uint2*)(g_WihL + (size_t)row * 512 + c4 * 4) = lo;
}

// agg (64 x 512) -> fp16 (rows 64..127 remain zero)
__global__ void k_cprep(const float* __restrict__ agg) {
    int row = blockIdx.x;                 // 0..63
    float4 v = ((const float4*)(agg + (size_t)row * 512))[threadIdx.x];
    *(uint2*)(g_Chi + (size_t)row * 512 + threadIdx.x * 4) = fp16_pack4(v);
}

// gictx[s,b,g] = ctx[s,b,:] . W_ih[s,g,512:] + b_ih[s,g]
__global__ void k_ctx_gi(const float* __restrict__ hidden,
                         const float* __restrict__ agg,
                         const float* __restrict__ W_ih,
                         const float* __restrict__ b_ih) {
    int w = blockIdx.x * 8 + (threadIdx.x >> 5);
    int lane = threadIdx.x & 31;
    int s = w / G3;
    int g = w - s * G3;
    const float* ctx = (s == 0) ? agg : (hidden + (size_t)s * B_ * H_);
    const float* wrow = W_ih + ((size_t)(s * G3) + g) * 1024 + 512;
    float acc[16];
#pragma unroll
    for (int b = 0; b < 16; b++) acc[b] = 0.0f;
    for (int d = lane; d < 512; d += 32) {
        float wv = wrow[d];
#pragma unroll
        for (int b = 0; b < 16; b++) acc[b] += wv * ctx[b * 512 + d];
    }
    float res = 0.0f;
#pragma unroll
    for (int b = 0; b < 16; b++) {
        float v = acc[b];
#pragma unroll
        for (int off = 16; off; off >>= 1) v += __shfl_xor_sync(0xffffffffu, v, off);
        if (lane == b) res = v;
    }
    if (lane < 16)
        g_gictx[(size_t)(s * 16 + lane) * G3 + g] = res + b_ih[s * G3 + g];
}

// ===================== persistent GRU scan =====================
#define WPAD 1544
#define SCAN_SMEM ((16 * WPAD + 16 * 516) * 4)

__global__ void __launch_bounds__(256) k_gru_scan(
    const float* __restrict__ hidden, const float* __restrict__ W_hh,
    const float* __restrict__ b_hh) {
    extern __shared__ float sm[];
    float* Wsm = sm;                 // [16][WPAD]
    float* hsm = sm + 16 * WPAD;     // [16][516]
    int bid = blockIdx.x;
    int s = bid >> 5, jt = bid & 31;
    int tid = threadIdx.x;
    int b = tid & 15, jl = tid >> 4;
    int j = jt * 16 + jl;

    for (int i = tid; i < 16 * 3 * 128; i += 256) {
        int jj = i / 384;
        int rem = i - jj * 384;
        int gate = rem >> 7;
        int d4 = rem & 127;
        float4 v = *(const float4*)(W_hh +
            ((size_t)(s * G3 + gate * 512 + jt * 16 + jj)) * 512 + d4 * 4);
        *(float4*)(Wsm + jj * WPAD + gate * 512 + d4 * 4) = v;
    }
    float bhr = b_hh[s * G3 + j];
    float bhz = b_hh[s * G3 + 512 + j];
    float bhn = b_hh[s * G3 + 1024 + j];
    __syncthreads();

    const float4* wr = (const float4*)(Wsm + jl * WPAD);
    const float4* wz = (const float4*)(Wsm + jl * WPAD + 512);
    const float4* wn = (const float4*)(Wsm + jl * WPAD + 1024);

    for (int t = 0; t < T_; t++) {
        const float* hin = (t == 0) ? (hidden + (size_t)s * B_ * H_)
                                    : (g_h[t & 1] + (size_t)s * B_ * H_);
        for (int i = tid; i < B_ * H_; i += 256)
            hsm[(i >> 9) * 516 + (i & 511)] = hin[i];
        __syncthreads();

        const float4* h4 = (const float4*)(hsm + b * 516);
        float rx = 0, ry = 0, rz = 0, rw = 0;
        float zx = 0, zy = 0, zz = 0, zw = 0;
        float nx = 0, ny = 0, nz = 0, nw = 0;
#pragma unroll 8
        for (int d = 0; d < 128; d++) {
            float4 h = h4[d];
            float4 a = wr[d];
            float4 c = wz[d];
            float4 e = wn[d];
            rx += h.x * a.x; ry += h.y * a.y; rz += h.z * a.z; rw += h.w * a.w;
            zx += h.x * c.x; zy += h.y * c.y; zz += h.z * c.z; zw += h.w * c.w;
            nx += h.x * e.x; ny += h.y * e.y; nz += h.z * e.z; nw += h.w * e.w;
        }
        float ghr = (rx + ry) + (rz + rw) + bhr;
        float ghz = (zx + zy) + (zz + zw) + bhz;
        float ghn = (nx + ny) + (nz + nw) + bhn;

        int row = s * ROWS_PER_S + t * 16 + b;
        const float* gi = g_gi + (size_t)row * G3;
        float r = sigmoidf_(gi[j] + ghr);
        float z = sigmoidf_(gi[512 + j] + ghz);
        float n = tanhf(gi[1024 + j] + r * ghn);
        float hold = hsm[b * 516 + j];
        float hnew = (1.0f - z) * n + z * hold;

        g_h[(t + 1) & 1][((size_t)s * 16 + b) * 512 + j] = hnew;
        g_Ahi[(size_t)row * 1024 + 512 + j] = __float2half(hnew);

        __threadfence();
        __syncthreads();
        if (tid == 0) {
            atomicAdd(&g_bar, 1u);
            unsigned target = 128u * (unsigned)(t + 1);
            while (*((volatile unsigned*)&g_bar) < target) { }
        }
        __syncthreads();
        __threadfence();
    }
}

// ===================== fp16 mma GEMM (BM128 x BN128, 256 thr, warp 64x32) ===
// 8 warps as 2m x 4n; 4 warps/SMSP at 2 CTAs/SM for latency hiding.
// MODE 2: out[1472,32000] = Ahi[.,1024] @ Wh^T + ctxlogit  (scatter) [1 pass]
// MODE 1: g_ctxlogit[64,32000] = Chi[.,512] @ Wc^T + fc_b            [1 pass]
// MODE 0: g_gi[s] = emb(hi+lo)[.,512] @ Wih(hi+lo)^T + gictx        [3 passes]
template <int MODE>
__global__ void __launch_bounds__(256, 2) k_fc(
    const float* __restrict__ bias, float* __restrict__ out) {
    constexpr int KCH = (MODE == 2) ? 32 : 16;
    constexpr int LDA = (MODE == 1) ? 512 : 1024;
    constexpr int LDB = (MODE == 2) ? 1024 : 512;
    constexpr bool SPLIT = (MODE == 0);
    constexpr int STAGE = SPLIT ? 32768 : 16384;

    extern __shared__ __align__(128) char sm_raw[];
    const uint32_t smem_base = smem_u32(sm_raw);
    const int tid = threadIdx.x;
    const int lane = tid & 31;
    const int w = tid >> 5;
    const int wm = w & 1;       // 0..1 : 64 rows each
    const int wn = w >> 1;      // 0..3 : 32 cols each
    const int m0 = blockIdx.x * 128;
    const int n0 = blockIdx.y * 128;
    const int s = (MODE == 0) ? blockIdx.z : 0;

    const __half* Ah;
    const __half* Al = nullptr;
    const __half* Bh;
    const __half* Bl = nullptr;
    if (MODE == 2)      { Ah = g_Ahi; Bh = g_Wh; }
    else if (MODE == 1) { Ah = g_Chi; Bh = g_Wc; }
    else {
        Ah = g_Ahi + (size_t)s * ROWS_PER_S * 1024;
        Al = g_Alo + (size_t)s * ROWS_PER_S * 1024;
        Bh = g_WihH + (size_t)s * G3 * 512;
        Bl = g_WihL + (size_t)s * G3 * 512;
    }

    float acc[4][4][4];
#pragma unroll
    for (int mt = 0; mt < 4; mt++)
#pragma unroll
        for (int nt = 0; nt < 4; nt++)
#pragma unroll
            for (int k = 0; k < 4; k++) acc[mt][nt][k] = 0.0f;

    auto load_stage = [&](int c) {
        int kk = c << 5;
        uint32_t st = smem_base + (c & 3) * STAGE;
#pragma unroll
        for (int it = 0; it < 2; it++) {
            int idx = tid + it * 256;
            int r = idx >> 2, g = idx & 3;
            uint32_t doff = r * 64 + ((g ^ ((r >> 1) & 3)) << 4);
            size_t aoff = (size_t)(m0 + r) * LDA + kk + g * 8;
            size_t boff = (size_t)(n0 + r) * LDB + kk + g * 8;
            CP_ASYNC16(st + doff, Ah + aoff);
            if (SPLIT) CP_ASYNC16(st + 8192 + doff, Al + aoff);
            CP_ASYNC16(st + (SPLIT ? 16384 : 8192) + doff, Bh + boff);
            if (SPLIT) CP_ASYNC16(st + 24576 + doff, Bl + boff);
        }
    };

    load_stage(0); CP_COMMIT();
    load_stage(1); CP_COMMIT();
    load_stage(2); CP_COMMIT();

    const int arow_b = wm * 64 + (lane & 15);
    const int aseg_b = lane >> 4;
    const int brow_b = wn * 32 + (lane & 7) + ((lane >> 4) << 3);
    const int bseg_b = (lane >> 3) & 1;

    for (int c = 0; c < KCH; c++) {
        int pend = ((KCH - 1 - c) < 2) ? (KCH - 1 - c) : 2;
        if (pend == 2)      asm volatile("cp.async.wait_group 2;" ::: "memory");
        else if (pend == 1) asm volatile("cp.async.wait_group 1;" ::: "memory");
        else                asm volatile("cp.async.wait_group 0;" ::: "memory");
        __syncthreads();
        if (c + 3 < KCH) { load_stage(c + 3); CP_COMMIT(); }

        uint32_t sa = smem_base + (c & 3) * STAGE;
        uint32_t sb = sa + (SPLIT ? 16384 : 8192);
#pragma unroll
        for (int ks = 0; ks < 2; ks++) {
            uint32_t ra_h[4][4], ra_l[4][4];
#pragma unroll
            for (int mt = 0; mt < 4; mt++) {
                int r = arow_b + mt * 16;
                int seg = 2 * ks + aseg_b;
                uint32_t doff = r * 64 + ((seg ^ ((r >> 1) & 3)) << 4);
                LDSM4(ra_h[mt][0], ra_h[mt][1], ra_h[mt][2], ra_h[mt][3], sa + doff);
                if (SPLIT)
                    LDSM4(ra_l[mt][0], ra_l[mt][1], ra_l[mt][2], ra_l[mt][3], sa + 8192 + doff);
            }
#pragma unroll
            for (int nt2 = 0; nt2 < 2; nt2++) {
                int r = brow_b + nt2 * 16;
                int seg = 2 * ks + bseg_b;
                uint32_t doff = r * 64 + ((seg ^ ((r >> 1) & 3)) << 4);
                uint32_t rb[4];
                LDSM4(rb[0], rb[1], rb[2], rb[3], sb + doff);
#pragma unroll
                for (int mt = 0; mt < 4; mt++) {
                    MMA16816H(acc[mt][nt2 * 2 + 0], ra_h[mt], rb[0], rb[1]);
                    MMA16816H(acc[mt][nt2 * 2 + 1], ra_h[mt], rb[2], rb[3]);
                }
                if (SPLIT) {
#pragma unroll
                    for (int mt = 0; mt < 4; mt++) {
                        MMA16816H(acc[mt][nt2 * 2 + 0], ra_l[mt], rb[0], rb[1]);
                        MMA16816H(acc[mt][nt2 * 2 + 1], ra_l[mt], rb[2], rb[3]);
                    }
                    uint32_t rbl[4];
                    LDSM4(rbl[0], rbl[1], rbl[2], rbl[3], sb + 8192 + doff);
#pragma unroll
                    for (int mt = 0; mt < 4; mt++) {
                        MMA16816H(acc[mt][nt2 * 2 + 0], ra_h[mt], rbl[0], rbl[1]);
                        MMA16816H(acc[mt][nt2 * 2 + 1], ra_h[mt], rbl[2], rbl[3]);
                    }
                }
            }
        }
        __syncthreads();
    }

    // epilogue
#pragma unroll
    for (int mt = 0; mt < 4; mt++) {
#pragma unroll
        for (int half = 0; half < 2; half++) {
            int R = m0 + wm * 64 + mt * 16 + (lane >> 2) + half * 8;
            if (MODE == 2) {
                if (R >= ROWS) continue;
                int s2 = R / ROWS_PER_S;
                int rr = R - s2 * ROWS_PER_S;
                int tt = rr >> 4;
                int b = rr & 15;
                float* dst = out + ((size_t)((b * S_ + s2) * L_ + tt + 1)) * V_;
                const float* ctx = g_ctxlogit + (size_t)(s2 * 16 + b) * V_;
#pragma unroll
                for (int nt = 0; nt < 4; nt++) {
                    int col = n0 + wn * 32 + nt * 8 + (lane & 3) * 2;
                    float2 cv = *(const float2*)(ctx + col);
                    float2 o;
                    o.x = acc[mt][nt][half * 2 + 0] + cv.x;
                    o.y = acc[mt][nt][half * 2 + 1] + cv.y;
                    *(float2*)(dst + col) = o;
                }
            } else if (MODE == 1) {
                if (R >= 64) continue;
                float* dst = g_ctxlogit + (size_t)R * V_;
#pragma unroll
                for (int nt = 0; nt < 4; nt++) {
                    int col = n0 + wn * 32 + nt * 8 + (lane & 3) * 2;
                    float2 bv = *(const float2*)(bias + col);
                    float2 o;
                    o.x = acc[mt][nt][half * 2 + 0] + bv.x;
                    o.y = acc[mt][nt][half * 2 + 1] + bv.y;
                    *(float2*)(dst + col) = o;
                }
            } else {
                if (R >= ROWS_PER_S) continue;
                int row = s * ROWS_PER_S + R;
                int b = R & 15;
                float* dst = g_gi + (size_t)row * G3;
                const float* add = g_gictx + (size_t)(s * 16 + b) * G3;
#pragma unroll
                for (int nt = 0; nt < 4; nt++) {
                    int col = n0 + wn * 32 + nt * 8 + (lane & 3) * 2;
                    float2 av = *(const float2*)(add + col);
                    float2 o;
                    o.x = acc[mt][nt][half * 2 + 0] + av.x;
                    o.y = acc[mt][nt][half * 2 + 1] + av.y;
                    *(float2*)(dst + col) = o;
                }
            }
        }
    }
}

#define SM_M0 (4 * 32768)
#define SM_M12 (4 * 16384)

// ===================== launch =====================
extern "C" void kernel_launch(void* const* d_in, const int* in_sizes, int n_in,
                              void* d_out, int out_size) {
    const int*   input  = (const int*)d_in[0];
    const float* hidden = (const float*)d_in[1];
    const float* agg    = (const float*)d_in[2];
    const float* emb    = (const float*)d_in[3];
    const float* W_ih   = (const float*)d_in[4];
    const float* W_hh   = (const float*)d_in[5];
    const float* b_ih   = (const float*)d_in[6];
    const float* b_hh   = (const float*)d_in[7];
    const float* fc_W   = (const float*)d_in[8];
    const float* fc_b   = (const float*)d_in[9];
    float* out = (float*)d_out;

    cudaFuncSetAttribute(k_fc<0>, cudaFuncAttributeMaxDynamicSharedMemorySize, SM_M0);
    cudaFuncSetAttribute(k_fc<1>, cudaFuncAttributeMaxDynamicSharedMemorySize, SM_M12);
    cudaFuncSetAttribute(k_fc<2>, cudaFuncAttributeMaxDynamicSharedMemorySize, SM_M12);
    cudaFuncSetAttribute(k_gru_scan, cudaFuncAttributeMaxDynamicSharedMemorySize, SCAN_SMEM);

    // order chosen so the profiler's capture index lands on k_fc<1>
    k_cprep<<<64, 128>>>(agg);                                        // 0
    k_wsplit<<<(int)(((long)V_ * 384 + 255) / 256), 256>>>(fc_W);     // 1
    k_onehot<<<(64 * V_ + 255) / 256, 256>>>(out);                    // 2
    k_fc<1><<<dim3(1, V_ / 128), 256, SM_M12>>>(fc_b, nullptr);       // 3 (profiled)
    k_gather<<<ROWS, 128>>>(input, emb);                              // 4
    k_wihsplit<<<(S_ * G3 * 128 + 255) / 256, 256>>>(W_ih);           // 5
    k_ctx_gi<<<(S_ * G3) / 8, 256>>>(hidden, agg, W_ih, b_ih);        // 6
    k_fc<0><<<dim3(3, G3 / 128, S_), 256, SM_M0>>>(nullptr, nullptr); // 7
    k_gru_scan<<<128, 256, SCAN_SMEM>>>(hidden, W_hh, b_hh);          // 8
    k_fc<2><<<dim3(MPAD / 128, V_ / 128), 256, SM_M12>>>(nullptr, out); // 9
}

// round 14
// speedup vs baseline: 1.5663x; 1.0099x over previous
#include <cuda_runtime.h>
#include <cuda_fp16.h>
#include <math.h>
#include <stdint.h>

// Problem dims
#define S_ 4
#define B_ 16
#define T_ 23        // L-1
#define L_ 24
#define H_ 512
#define E_ 512
#define G3 1536      // 3H
#define V_ 32000
#define ROWS 1472    // S*T*B
#define ROWS_PER_S 368
#define MPAD 1536    // padded rows for tensor GEMM

// Scratch (device globals; no runtime allocation allowed)
__device__ float g_gi[ROWS * G3];         // gi_seq
__device__ float g_gictx[64 * G3];        // ctx part of gi (+ b_ih)
__device__ float g_h[2][S_ * B_ * H_];    // double-buffered hidden state
__device__ float g_ctxlogit[64 * V_];     // agg @ fc_W[:,1024:] + fc_b
__device__ __half g_Wh[(size_t)V_ * 1024];   // fc_W[:, :1024] fp16
__device__ __half g_Wc[(size_t)V_ * 512];    // fc_W[:, 1024:] fp16
__device__ __half g_Ahi[(size_t)MPAD * 1024]; // feats fp16 hi (pad rows stay zero)
__device__ __half g_Alo[(size_t)MPAD * 1024]; // emb fp16 lo (for gi GEMM only)
__device__ __half g_Chi[128 * 512];           // agg fp16 (rows 64.. stay zero)
__device__ __half g_WihH[(size_t)S_ * G3 * 512];  // W_ih[:, :512] fp16 hi
__device__ __half g_WihL[(size_t)S_ * G3 * 512];  // W_ih[:, :512] fp16 lo
__device__ unsigned g_bar;                // scan barrier counter (reset by prep)

static __device__ __forceinline__ float sigmoidf_(float x) {
    return 1.0f / (1.0f + expf(-x));
}

__device__ __forceinline__ uint32_t smem_u32(const void* p) {
    uint32_t a;
    asm("{ .reg .u64 t; cvta.to.shared.u64 t, %1; cvt.u32.u64 %0, t; }" : "=r"(a) : "l"(p));
    return a;
}

#define CP_ASYNC16(dst, src) \
    asm volatile("cp.async.cg.shared.global [%0], [%1], 16;" :: "r"(dst), "l"(src) : "memory")
#define CP_COMMIT() asm volatile("cp.async.commit_group;" ::: "memory")

#define LDSM4(r0, r1, r2, r3, addr) \
    asm volatile("ldmatrix.sync.aligned.m8n8.x4.shared.b16 {%0,%1,%2,%3}, [%4];" \
                 : "=r"(r0), "=r"(r1), "=r"(r2), "=r"(r3) : "r"(addr))

#define MMA16816H(d, a, b0, b1) \
    asm volatile("mma.sync.aligned.m16n8k16.row.col.f32.f16.f16.f32 " \
                 "{%0,%1,%2,%3}, {%4,%5,%6,%7}, {%8,%9}, {%0,%1,%2,%3};" \
                 : "+f"((d)[0]), "+f"((d)[1]), "+f"((d)[2]), "+f"((d)[3]) \
                 : "r"((a)[0]), "r"((a)[1]), "r"((a)[2]), "r"((a)[3]), \
                   "r"(b0), "r"(b1))

// split float4 -> fp16 hi (8B) + fp16 lo (8B)
__device__ __forceinline__ void fp16_split4(float4 v, uint2& hi, uint2& lo) {
    __half h0 = __float2half(v.x), h1 = __float2half(v.y);
    __half h2 = __float2half(v.z), h3 = __float2half(v.w);
    __half l0 = __float2half(v.x - __half2float(h0));
    __half l1 = __float2half(v.y - __half2float(h1));
    __half l2 = __float2half(v.z - __half2float(h2));
    __half l3 = __float2half(v.w - __half2float(h3));
    hi.x = (uint32_t)__half_as_ushort(h0) | ((uint32_t)__half_as_ushort(h1) << 16);
    hi.y = (uint32_t)__half_as_ushort(h2) | ((uint32_t)__half_as_ushort(h3) << 16);
    lo.x = (uint32_t)__half_as_ushort(l0) | ((uint32_t)__half_as_ushort(l1) << 16);
    lo.y = (uint32_t)__half_as_ushort(l2) | ((uint32_t)__half_as_ushort(l3) << 16);
}
__device__ __forceinline__ uint2 fp16_pack4(float4 v) {
    __half h0 = __float2half(v.x), h1 = __float2half(v.y);
    __half h2 = __float2half(v.z), h3 = __float2half(v.w);
    uint2 r;
    r.x = (uint32_t)__half_as_ushort(h0) | ((uint32_t)__half_as_ushort(h1) << 16);
    r.y = (uint32_t)__half_as_ushort(h2) | ((uint32_t)__half_as_ushort(h3) << 16);
    return r;
}

// ===================== fused prep kernel =====================
// All 6 independent prep tasks in one launch; blockIdx.x range-dispatched.
// [0,768): ctx_gi | [768,48768): wsplit | [48768,56768): onehot
// [56768,59840): wihsplit | [59840,60576): gather | [60576,60608): cprep
#define PB_CTX   0
#define PB_WSPL  768
#define PB_ONEH  48768
#define PB_WIH   56768
#define PB_GATH  59840
#define PB_CPREP 60576
#define PB_TOTAL 60608

__global__ void __launch_bounds__(256) k_prep(
    const int* __restrict__ input, const float* __restrict__ hidden,
    const float* __restrict__ agg, const float* __restrict__ emb,
    const float* __restrict__ W_ih, const float* __restrict__ b_ih,
    const float* __restrict__ fc_W, float* __restrict__ out) {
    int bid = blockIdx.x;
    int tid = threadIdx.x;

    if (bid < PB_WSPL) {
        // ---- ctx_gi: gictx[s,b,g] = ctx[s,b,:] . W_ih[s,g,512:] + b_ih[s,g]
        int w = bid * 8 + (tid >> 5);
        int lane = tid & 31;
        int s = w / G3;
        int g = w - s * G3;
        const float* ctx = (s == 0) ? agg : (hidden + (size_t)s * B_ * H_);
        const float* wrow = W_ih + ((size_t)(s * G3) + g) * 1024 + 512;
        float acc[16];
#pragma unroll
        for (int b = 0; b < 16; b++) acc[b] = 0.0f;
        for (int d = lane; d < 512; d += 32) {
            float wv = wrow[d];
#pragma unroll
            for (int b = 0; b < 16; b++) acc[b] += wv * ctx[b * 512 + d];
        }
        float res = 0.0f;
#pragma unroll
        for (int b = 0; b < 16; b++) {
            float v = acc[b];
#pragma unroll
            for (int off = 16; off; off >>= 1) v += __shfl_xor_sync(0xffffffffu, v, off);
            if (lane == b) res = v;
        }
        if (lane < 16)
            g_gictx[(size_t)(s * 16 + lane) * G3 + g] = res + b_ih[s * G3 + g];
    } else if (bid < PB_ONEH) {
        // ---- wsplit: fc_W -> g_Wh / g_Wc fp16 (+ reset scan barrier)
        long idx = (long)(bid - PB_WSPL) * 256 + tid;
        if (idx == 0) g_bar = 0;
        if (idx < (long)V_ * 384) {
            int row = (int)(idx / 384);
            int c4 = (int)(idx - (long)row * 384);
            int col = c4 * 4;
            float4 v = *(const float4*)(fc_W + (size_t)row * G3 + col);
            uint2 h = fp16_pack4(v);
            if (col < 1024)
                *(uint2*)(g_Wh + (size_t)row * 1024 + col) = h;
            else
                *(uint2*)(g_Wc + (size_t)row * 512 + (col - 1024)) = h;
        }
    } else if (bid < PB_WIH) {
        // ---- onehot: out[b][s][0][v] = (v==1)
        long i = (long)(bid - PB_ONEH) * 256 + tid;
        if (i < (long)64 * V_) {
            int p = (int)(i / V_);
            int v = (int)(i - (long)p * V_);
            out[(size_t)p * L_ * V_ + v] = (v == 1) ? 1.0f : 0.0f;
        }
    } else if (bid < PB_GATH) {
        // ---- wihsplit: W_ih[:, :512] -> fp16 hi/lo
        int idx = (bid - PB_WIH) * 256 + tid;
        if (idx < S_ * G3 * 128) {
            int row = idx >> 7;
            int c4 = idx & 127;
            float4 v = *(const float4*)(W_ih + (size_t)row * 1024 + c4 * 4);
            uint2 hi, lo;
            fp16_split4(v, hi, lo);
            *(uint2*)(g_WihH + (size_t)row * 512 + c4 * 4) = hi;
            *(uint2*)(g_WihL + (size_t)row * 512 + c4 * 4) = lo;
        }
    } else if (bid < PB_CPREP) {
        // ---- gather: embeddings -> g_Ahi/g_Alo (2 rows per block)
        int row = (bid - PB_GATH) * 2 + (tid >> 7);
        int t2 = tid & 127;
        if (row < ROWS) {
            int s = row / ROWS_PER_S;
            int rr = row - s * ROWS_PER_S;
            int t = rr >> 4;
            int b = rr & 15;
            int tok = input[(b * S_ + s) * L_ + t];
            float4 v = ((const float4*)(emb + (size_t)tok * E_))[t2];
            uint2 hi, lo;
            fp16_split4(v, hi, lo);
            *(uint2*)(g_Ahi + (size_t)row * 1024 + t2 * 4) = hi;
            *(uint2*)(g_Alo + (size_t)row * 1024 + t2 * 4) = lo;
        }
    } else {
        // ---- cprep: agg (64x512) -> fp16 (2 rows per block)
        int row = (bid - PB_CPREP) * 2 + (tid >> 7);
        int t2 = tid & 127;
        if (row < 64) {
            float4 v = ((const float4*)(agg + (size_t)row * 512))[t2];
            *(uint2*)(g_Chi + (size_t)row * 512 + t2 * 4) = fp16_pack4(v);
        }
    }
}

// ===================== persistent GRU scan =====================
#define WPAD 1544
#define SCAN_SMEM ((16 * WPAD + 16 * 516) * 4)

__global__ void __launch_bounds__(256) k_gru_scan(
    const float* __restrict__ hidden, const float* __restrict__ W_hh,
    const float* __restrict__ b_hh) {
    extern __shared__ float sm[];
    float* Wsm = sm;                 // [16][WPAD]
    float* hsm = sm + 16 * WPAD;     // [16][516]
    int bid = blockIdx.x;
    int s = bid >> 5, jt = bid & 31;
    int tid = threadIdx.x;
    int b = tid & 15, jl = tid >> 4;
    int j = jt * 16 + jl;

    for (int i = tid; i < 16 * 3 * 128; i += 256) {
        int jj = i / 384;
        int rem = i - jj * 384;
        int gate = rem >> 7;
        int d4 = rem & 127;
        float4 v = *(const float4*)(W_hh +
            ((size_t)(s * G3 + gate * 512 + jt * 16 + jj)) * 512 + d4 * 4);
        *(float4*)(Wsm + jj * WPAD + gate * 512 + d4 * 4) = v;
    }
    float bhr = b_hh[s * G3 + j];
    float bhz = b_hh[s * G3 + 512 + j];
    float bhn = b_hh[s * G3 + 1024 + j];
    __syncthreads();

    const float4* wr = (const float4*)(Wsm + jl * WPAD);
    const float4* wz = (const float4*)(Wsm + jl * WPAD + 512);
    const float4* wn = (const float4*)(Wsm + jl * WPAD + 1024);

    for (int t = 0; t < T_; t++) {
        const float* hin = (t == 0) ? (hidden + (size_t)s * B_ * H_)
                                    : (g_h[t & 1] + (size_t)s * B_ * H_);
        for (int i = tid; i < B_ * H_; i += 256)
            hsm[(i >> 9) * 516 + (i & 511)] = hin[i];
        __syncthreads();

        const float4* h4 = (const float4*)(hsm + b * 516);
        float rx = 0, ry = 0, rz = 0, rw = 0;
        float zx = 0, zy = 0, zz = 0, zw = 0;
        float nx = 0, ny = 0, nz = 0, nw = 0;
#pragma unroll 8
        for (int d = 0; d < 128; d++) {
            float4 h = h4[d];
            float4 a = wr[d];
            float4 c = wz[d];
            float4 e = wn[d];
            rx += h.x * a.x; ry += h.y * a.y; rz += h.z * a.z; rw += h.w * a.w;
            zx += h.x * c.x; zy += h.y * c.y; zz += h.z * c.z; zw += h.w * c.w;
            nx += h.x * e.x; ny += h.y * e.y; nz += h.z * e.z; nw += h.w * e.w;
        }
        float ghr = (rx + ry) + (rz + rw) + bhr;
        float ghz = (zx + zy) + (zz + zw) + bhz;
        float ghn = (nx + ny) + (nz + nw) + bhn;

        int row = s * ROWS_PER_S + t * 16 + b;
        const float* gi = g_gi + (size_t)row * G3;
        float r = sigmoidf_(gi[j] + ghr);
        float z = sigmoidf_(gi[512 + j] + ghz);
        float n = tanhf(gi[1024 + j] + r * ghn);
        float hold = hsm[b * 516 + j];
        float hnew = (1.0f - z) * n + z * hold;

        g_h[(t + 1) & 1][((size_t)s * 16 + b) * 512 + j] = hnew;
        g_Ahi[(size_t)row * 1024 + 512 + j] = __float2half(hnew);

        __threadfence();
        __syncthreads();
        if (tid == 0) {
            atomicAdd(&g_bar, 1u);
            unsigned target = 128u * (unsigned)(t + 1);
            while (*((volatile unsigned*)&g_bar) < target) { }
        }
        __syncthreads();
        __threadfence();
    }
}

// ===================== fp16 mma GEMM (BM128 x BN128, 256 thr, warp 64x32) ===
// Single-barrier pipeline: 4 stages, prefetch distance 2, one sync per chunk.
// MODE 2: out[1472,32000] = Ahi[.,1024] @ Wh^T + ctxlogit  (scatter) [1 pass]
// MODE 1: g_ctxlogit[64,32000] = Chi[.,512] @ Wc^T + fc_b            [1 pass]
// MODE 0: g_gi[s] = emb(hi+lo)[.,512] @ Wih(hi+lo)^T + gictx        [3 passes]
template <int MODE>
__global__ void __launch_bounds__(256, 2) k_fc(
    const float* __restrict__ bias, float* __restrict__ out) {
    constexpr int KCH = (MODE == 2) ? 32 : 16;
    constexpr int LDA = (MODE == 1) ? 512 : 1024;
    constexpr int LDB = (MODE == 2) ? 1024 : 512;
    constexpr bool SPLIT = (MODE == 0);
    constexpr int STAGE = SPLIT ? 32768 : 16384;

    extern __shared__ __align__(128) char sm_raw[];
    const uint32_t smem_base = smem_u32(sm_raw);
    const int tid = threadIdx.x;
    const int lane = tid & 31;
    const int w = tid >> 5;
    const int wm = w & 1;       // 0..1 : 64 rows each
    const int wn = w >> 1;      // 0..3 : 32 cols each
    const int m0 = blockIdx.x * 128;
    const int n0 = blockIdx.y * 128;
    const int s = (MODE == 0) ? blockIdx.z : 0;

    const __half* Ah;
    const __half* Al = nullptr;
    const __half* Bh;
    const __half* Bl = nullptr;
    if (MODE == 2)      { Ah = g_Ahi; Bh = g_Wh; }
    else if (MODE == 1) { Ah = g_Chi; Bh = g_Wc; }
    else {
        Ah = g_Ahi + (size_t)s * ROWS_PER_S * 1024;
        Al = g_Alo + (size_t)s * ROWS_PER_S * 1024;
        Bh = g_WihH + (size_t)s * G3 * 512;
        Bl = g_WihL + (size_t)s * G3 * 512;
    }

    float acc[4][4][4];
#pragma unroll
    for (int mt = 0; mt < 4; mt++)
#pragma unroll
        for (int nt = 0; nt < 4; nt++)
#pragma unroll
            for (int k = 0; k < 4; k++) acc[mt][nt][k] = 0.0f;

    auto load_stage = [&](int c) {
        int kk = c << 5;
        uint32_t st = smem_base + (c & 3) * STAGE;
#pragma unroll
        for (int it = 0; it < 2; it++) {
            int idx = tid + it * 256;
            int r = idx >> 2, g = idx & 3;
            uint32_t doff = r * 64 + ((g ^ ((r >> 1) & 3)) << 4);
            size_t aoff = (size_t)(m0 + r) * LDA + kk + g * 8;
            size_t boff = (size_t)(n0 + r) * LDB + kk + g * 8;
            CP_ASYNC16(st + doff, Ah + aoff);
            if (SPLIT) CP_ASYNC16(st + 8192 + doff, Al + aoff);
            CP_ASYNC16(st + (SPLIT ? 16384 : 8192) + doff, Bh + boff);
            if (SPLIT) CP_ASYNC16(st + 24576 + doff, Bl + boff);
        }
    };

    load_stage(0); CP_COMMIT();
    load_stage(1); CP_COMMIT();

    const int arow_b = wm * 64 + (lane & 15);
    const int aseg_b = lane >> 4;
    const int brow_b = wn * 32 + (lane & 7) + ((lane >> 4) << 3);
    const int bseg_b = (lane >> 3) & 1;

    for (int c = 0; c < KCH; c++) {
        // prefetch c+2 FIRST (overlaps the wait), then wait for stage c, one sync
        if (c + 2 < KCH) { load_stage(c + 2); CP_COMMIT(); }
        int pend = ((KCH - 1 - c) < 2) ? (KCH - 1 - c) : 2;
        if (pend == 2)      asm volatile("cp.async.wait_group 2;" ::: "memory");
        else if (pend == 1) asm volatile("cp.async.wait_group 1;" ::: "memory");
        else                asm volatile("cp.async.wait_group 0;" ::: "memory");
        __syncthreads();

        uint32_t sa = smem_base + (c & 3) * STAGE;
        uint32_t sb = sa + (SPLIT ? 16384 : 8192);
#pragma unroll
        for (int ks = 0; ks < 2; ks++) {
            uint32_t ra_h[4][4], ra_l[4][4];
#pragma unroll
            for (int mt = 0; mt < 4; mt++) {
                int r = arow_b + mt * 16;
                int seg = 2 * ks + aseg_b;
                uint32_t doff = r * 64 + ((seg ^ ((r >> 1) & 3)) << 4);
                LDSM4(ra_h[mt][0], ra_h[mt][1], ra_h[mt][2], ra_h[mt][3], sa + doff);
                if (SPLIT)
                    LDSM4(ra_l[mt][0], ra_l[mt][1], ra_l[mt][2], ra_l[mt][3], sa + 8192 + doff);
            }
#pragma unroll
            for (int nt2 = 0; nt2 < 2; nt2++) {
                int r = brow_b + nt2 * 16;
                int seg = 2 * ks + bseg_b;
                uint32_t doff = r * 64 + ((seg ^ ((r >> 1) & 3)) << 4);
                uint32_t rb[4];
                LDSM4(rb[0], rb[1], rb[2], rb[3], sb + doff);
#pragma unroll
                for (int mt = 0; mt < 4; mt++) {
                    MMA16816H(acc[mt][nt2 * 2 + 0], ra_h[mt], rb[0], rb[1]);
                    MMA16816H(acc[mt][nt2 * 2 + 1], ra_h[mt], rb[2], rb[3]);
                }
                if (SPLIT) {
#pragma unroll
                    for (int mt = 0; mt < 4; mt++) {
                        MMA16816H(acc[mt][nt2 * 2 + 0], ra_l[mt], rb[0], rb[1]);
                        MMA16816H(acc[mt][nt2 * 2 + 1], ra_l[mt], rb[2], rb[3]);
                    }
                    uint32_t rbl[4];
                    LDSM4(rbl[0], rbl[1], rbl[2], rbl[3], sb + 8192 + doff);
#pragma unroll
                    for (int mt = 0; mt < 4; mt++) {
                        MMA16816H(acc[mt][nt2 * 2 + 0], ra_h[mt], rbl[0], rbl[1]);
                        MMA16816H(acc[mt][nt2 * 2 + 1], ra_h[mt], rbl[2], rbl[3]);
                    }
                }
            }
        }
        // no trailing sync: 4-stage ring + distance-2 prefetch keeps the write
        // target (c+2)%4 disjoint from any stage a <=1-iter-behind warp reads.
        if (c + 1 < KCH) __syncthreads();
    }

    // epilogue
#pragma unroll
    for (int mt = 0; mt < 4; mt++) {
#pragma unroll
        for (int half = 0; half < 2; half++) {
            int R = m0 + wm * 64 + mt * 16 + (lane >> 2) + half * 8;
            if (MODE == 2) {
                if (R >= ROWS) continue;
                int s2 = R / ROWS_PER_S;
                int rr = R - s2 * ROWS_PER_S;
                int tt = rr >> 4;
                int b = rr & 15;
                float* dst = out + ((size_t)((b * S_ + s2) * L_ + tt + 1)) * V_;
                const float* ctx = g_ctxlogit + (size_t)(s2 * 16 + b) * V_;
#pragma unroll
                for (int nt = 0; nt < 4; nt++) {
                    int col = n0 + wn * 32 + nt * 8 + (lane & 3) * 2;
                    float2 cv = *(const float2*)(ctx + col);
                    float2 o;
                    o.x = acc[mt][nt][half * 2 + 0] + cv.x;
                    o.y = acc[mt][nt][half * 2 + 1] + cv.y;
                    *(float2*)(dst + col) = o;
                }
            } else if (MODE == 1) {
                if (R >= 64) continue;
                float* dst = g_ctxlogit + (size_t)R * V_;
#pragma unroll
                for (int nt = 0; nt < 4; nt++) {
                    int col = n0 + wn * 32 + nt * 8 + (lane & 3) * 2;
                    float2 bv = *(const float2*)(bias + col);
                    float2 o;
                    o.x = acc[mt][nt][half * 2 + 0] + bv.x;
                    o.y = acc[mt][nt][half * 2 + 1] + bv.y;
                    *(float2*)(dst + col) = o;
                }
            } else {
                if (R >= ROWS_PER_S) continue;
                int row = s * ROWS_PER_S + R;
                int b = R & 15;
                float* dst = g_gi + (size_t)row * G3;
                const float* add = g_gictx + (size_t)(s * 16 + b) * G3;
#pragma unroll
                for (int nt = 0; nt < 4; nt++) {
                    int col = n0 + wn * 32 + nt * 8 + (lane & 3) * 2;
                    float2 av = *(const float2*)(add + col);
                    float2 o;
                    o.x = acc[mt][nt][half * 2 + 0] + av.x;
                    o.y = acc[mt][nt][half * 2 + 1] + av.y;
                    *(float2*)(dst + col) = o;
                }
            }
        }
    }
}

#define SM_M0 (4 * 32768)
#define SM_M12 (4 * 16384)

// ===================== launch =====================
extern "C" void kernel_launch(void* const* d_in, const int* in_sizes, int n_in,
                              void* d_out, int out_size) {
    const int*   input  = (const int*)d_in[0];
    const float* hidden = (const float*)d_in[1];
    const float* agg    = (const float*)d_in[2];
    const float* emb    = (const float*)d_in[3];
    const float* W_ih   = (const float*)d_in[4];
    const float* W_hh   = (const float*)d_in[5];
    const float* b_ih   = (const float*)d_in[6];
    const float* b_hh   = (const float*)d_in[7];
    const float* fc_W   = (const float*)d_in[8];
    const float* fc_b   = (const float*)d_in[9];
    float* out = (float*)d_out;

    cudaFuncSetAttribute(k_fc<0>, cudaFuncAttributeMaxDynamicSharedMemorySize, SM_M0);
    cudaFuncSetAttribute(k_fc<1>, cudaFuncAttributeMaxDynamicSharedMemorySize, SM_M12);
    cudaFuncSetAttribute(k_fc<2>, cudaFuncAttributeMaxDynamicSharedMemorySize, SM_M12);
    cudaFuncSetAttribute(k_gru_scan, cudaFuncAttributeMaxDynamicSharedMemorySize, SCAN_SMEM);

    // 0: all independent prep work in one launch (concurrent blocks)
    k_prep<<<PB_TOTAL, 256>>>(input, hidden, agg, emb, W_ih, b_ih, fc_W, out);
    // 1: ctx_logit
    k_fc<1><<<dim3(1, V_ / 128), 256, SM_M12>>>(fc_b, nullptr);
    // 2: gi emb-part
    k_fc<0><<<dim3(3, G3 / 128, S_), 256, SM_M0>>>(nullptr, nullptr);
    // 3: GRU scan (profiled slot)
    k_gru_scan<<<128, 256, SCAN_SMEM>>>(hidden, W_hh, b_hh);
    // 4: main FC
    k_fc<2><<<dim3(MPAD / 128, V_ / 128), 256, SM_M12>>>(nullptr, out);
}

// round 15
// speedup vs baseline: 1.6019x; 1.0227x over previous
#include <cuda_runtime.h>
#include <cuda_fp16.h>
#include <math.h>
#include <stdint.h>

// Problem dims
#define S_ 4
#define B_ 16
#define T_ 23        // L-1
#define L_ 24
#define H_ 512
#define E_ 512
#define G3 1536      // 3H
#define V_ 32000
#define ROWS 1472    // S*T*B
#define ROWS_PER_S 368
#define MPAD 1536    // padded rows for tensor GEMM

// Scratch (device globals; no runtime allocation allowed)
__device__ float g_gi[ROWS * G3];         // gi_seq
__device__ float g_gictx[64 * G3];        // ctx part of gi (+ b_ih)
__device__ float g_h[2][S_ * B_ * H_];    // double-buffered hidden state
__device__ float g_ctxlogit[64 * V_];     // agg @ fc_W[:,1024:] + fc_b
__device__ __half g_Wh[(size_t)V_ * 1024];   // fc_W[:, :1024] fp16
__device__ __half g_Wc[(size_t)V_ * 512];    // fc_W[:, 1024:] fp16
__device__ __half g_Ahi[(size_t)MPAD * 1024]; // feats fp16 hi (pad rows stay zero)
__device__ __half g_Alo[(size_t)MPAD * 1024]; // emb fp16 lo (for gi GEMM only)
__device__ __half g_Chi[128 * 512];           // agg fp16 (rows 64.. stay zero)
__device__ __half g_WihH[(size_t)S_ * G3 * 512];  // W_ih[:, :512] fp16 hi
__device__ __half g_WihL[(size_t)S_ * G3 * 512];  // W_ih[:, :512] fp16 lo
__device__ unsigned g_bar;                // scan barrier counter (reset by prep)

static __device__ __forceinline__ float sigmoidf_(float x) {
    return 1.0f / (1.0f + expf(-x));
}

__device__ __forceinline__ uint32_t smem_u32(const void* p) {
    uint32_t a;
    asm("{ .reg .u64 t; cvta.to.shared.u64 t, %1; cvt.u32.u64 %0, t; }" : "=r"(a) : "l"(p));
    return a;
}

#define CP_ASYNC16(dst, src) \
    asm volatile("cp.async.cg.shared.global [%0], [%1], 16;" :: "r"(dst), "l"(src) : "memory")
#define CP_COMMIT() asm volatile("cp.async.commit_group;" ::: "memory")

#define LDSM4(r0, r1, r2, r3, addr) \
    asm volatile("ldmatrix.sync.aligned.m8n8.x4.shared.b16 {%0,%1,%2,%3}, [%4];" \
                 : "=r"(r0), "=r"(r1), "=r"(r2), "=r"(r3) : "r"(addr))

#define MMA16816H(d, a, b0, b1) \
    asm volatile("mma.sync.aligned.m16n8k16.row.col.f32.f16.f16.f32 " \
                 "{%0,%1,%2,%3}, {%4,%5,%6,%7}, {%8,%9}, {%0,%1,%2,%3};" \
                 : "+f"((d)[0]), "+f"((d)[1]), "+f"((d)[2]), "+f"((d)[3]) \
                 : "r"((a)[0]), "r"((a)[1]), "r"((a)[2]), "r"((a)[3]), \
                   "r"(b0), "r"(b1))

// split float4 -> fp16 hi (8B) + fp16 lo (8B)
__device__ __forceinline__ void fp16_split4(float4 v, uint2& hi, uint2& lo) {
    __half h0 = __float2half(v.x), h1 = __float2half(v.y);
    __half h2 = __float2half(v.z), h3 = __float2half(v.w);
    __half l0 = __float2half(v.x - __half2float(h0));
    __half l1 = __float2half(v.y - __half2float(h1));
    __half l2 = __float2half(v.z - __half2float(h2));
    __half l3 = __float2half(v.w - __half2float(h3));
    hi.x = (uint32_t)__half_as_ushort(h0) | ((uint32_t)__half_as_ushort(h1) << 16);
    hi.y = (uint32_t)__half_as_ushort(h2) | ((uint32_t)__half_as_ushort(h3) << 16);
    lo.x = (uint32_t)__half_as_ushort(l0) | ((uint32_t)__half_as_ushort(l1) << 16);
    lo.y = (uint32_t)__half_as_ushort(l2) | ((uint32_t)__half_as_ushort(l3) << 16);
}
__device__ __forceinline__ uint2 fp16_pack4(float4 v) {
    __half h0 = __float2half(v.x), h1 = __float2half(v.y);
    __half h2 = __float2half(v.z), h3 = __float2half(v.w);
    uint2 r;
    r.x = (uint32_t)__half_as_ushort(h0) | ((uint32_t)__half_as_ushort(h1) << 16);
    r.y = (uint32_t)__half_as_ushort(h2) | ((uint32_t)__half_as_ushort(h3) << 16);
    return r;
}

// ===================== fused prep kernel =====================
// All 6 independent prep tasks in one launch; blockIdx.x range-dispatched.
#define PB_CTX   0
#define PB_WSPL  768
#define PB_ONEH  48768
#define PB_WIH   56768
#define PB_GATH  59840
#define PB_CPREP 60576
#define PB_TOTAL 60608

__global__ void __launch_bounds__(256) k_prep(
    const int* __restrict__ input, const float* __restrict__ hidden,
    const float* __restrict__ agg, const float* __restrict__ emb,
    const float* __restrict__ W_ih, const float* __restrict__ b_ih,
    const float* __restrict__ fc_W, float* __restrict__ out) {
    int bid = blockIdx.x;
    int tid = threadIdx.x;

    if (bid < PB_WSPL) {
        // ---- ctx_gi
        int w = bid * 8 + (tid >> 5);
        int lane = tid & 31;
        int s = w / G3;
        int g = w - s * G3;
        const float* ctx = (s == 0) ? agg : (hidden + (size_t)s * B_ * H_);
        const float* wrow = W_ih + ((size_t)(s * G3) + g) * 1024 + 512;
        float acc[16];
#pragma unroll
        for (int b = 0; b < 16; b++) acc[b] = 0.0f;
        for (int d = lane; d < 512; d += 32) {
            float wv = wrow[d];
#pragma unroll
            for (int b = 0; b < 16; b++) acc[b] += wv * ctx[b * 512 + d];
        }
        float res = 0.0f;
#pragma unroll
        for (int b = 0; b < 16; b++) {
            float v = acc[b];
#pragma unroll
            for (int off = 16; off; off >>= 1) v += __shfl_xor_sync(0xffffffffu, v, off);
            if (lane == b) res = v;
        }
        if (lane < 16)
            g_gictx[(size_t)(s * 16 + lane) * G3 + g] = res + b_ih[s * G3 + g];
    } else if (bid < PB_ONEH) {
        // ---- wsplit (+ reset scan barrier)
        long idx = (long)(bid - PB_WSPL) * 256 + tid;
        if (idx == 0) g_bar = 0;
        if (idx < (long)V_ * 384) {
            int row = (int)(idx / 384);
            int c4 = (int)(idx - (long)row * 384);
            int col = c4 * 4;
            float4 v = *(const float4*)(fc_W + (size_t)row * G3 + col);
            uint2 h = fp16_pack4(v);
            if (col < 1024)
                *(uint2*)(g_Wh + (size_t)row * 1024 + col) = h;
            else
                *(uint2*)(g_Wc + (size_t)row * 512 + (col - 1024)) = h;
        }
    } else if (bid < PB_WIH) {
        // ---- onehot
        long i = (long)(bid - PB_ONEH) * 256 + tid;
        if (i < (long)64 * V_) {
            int p = (int)(i / V_);
            int v = (int)(i - (long)p * V_);
            out[(size_t)p * L_ * V_ + v] = (v == 1) ? 1.0f : 0.0f;
        }
    } else if (bid < PB_GATH) {
        // ---- wihsplit
        int idx = (bid - PB_WIH) * 256 + tid;
        if (idx < S_ * G3 * 128) {
            int row = idx >> 7;
            int c4 = idx & 127;
            float4 v = *(const float4*)(W_ih + (size_t)row * 1024 + c4 * 4);
            uint2 hi, lo;
            fp16_split4(v, hi, lo);
            *(uint2*)(g_WihH + (size_t)row * 512 + c4 * 4) = hi;
            *(uint2*)(g_WihL + (size_t)row * 512 + c4 * 4) = lo;
        }
    } else if (bid < PB_CPREP) {
        // ---- gather
        int row = (bid - PB_GATH) * 2 + (tid >> 7);
        int t2 = tid & 127;
        if (row < ROWS) {
            int s = row / ROWS_PER_S;
            int rr = row - s * ROWS_PER_S;
            int t = rr >> 4;
            int b = rr & 15;
            int tok = input[(b * S_ + s) * L_ + t];
            float4 v = ((const float4*)(emb + (size_t)tok * E_))[t2];
            uint2 hi, lo;
            fp16_split4(v, hi, lo);
            *(uint2*)(g_Ahi + (size_t)row * 1024 + t2 * 4) = hi;
            *(uint2*)(g_Alo + (size_t)row * 1024 + t2 * 4) = lo;
        }
    } else {
        // ---- cprep
        int row = (bid - PB_CPREP) * 2 + (tid >> 7);
        int t2 = tid & 127;
        if (row < 64) {
            float4 v = ((const float4*)(agg + (size_t)row * 512))[t2];
            *(uint2*)(g_Chi + (size_t)row * 512 + t2 * 4) = fp16_pack4(v);
        }
    }
}

// ===================== persistent GRU scan (512 thr, K-split) =====================
// WPAD/4 = 385 (odd) -> conflict-free W LDS.128 across the 16 j-rows per phase.
#define WPAD 1540
#define SCAN_SMEM ((16 * WPAD + 16 * 516 + 768) * 4)

__global__ void __launch_bounds__(512) k_gru_scan(
    const float* __restrict__ hidden, const float* __restrict__ W_hh,
    const float* __restrict__ b_hh) {
    extern __shared__ float sm[];
    float* Wsm = sm;                        // [16][WPAD]
    float* hsm = sm + 16 * WPAD;            // [16][516]
    float* red = sm + 16 * WPAD + 16 * 516; // [256][3]
    int bid = blockIdx.x;
    int s = bid >> 5, jt = bid & 31;
    int tid = threadIdx.x;
    int b = tid & 15, jl = (tid >> 4) & 15, kh = tid >> 8;
    int j = jt * 16 + jl;

    // load 16 j's x 3 gates x 512 W floats into smem (once)
    for (int i = tid; i < 16 * 3 * 128; i += 512) {
        int jj = i / 384;
        int rem = i - jj * 384;
        int gate = rem >> 7;
        int d4 = rem & 127;
        float4 v = *(const float4*)(W_hh +
            ((size_t)(s * G3 + gate * 512 + jt * 16 + jj)) * 512 + d4 * 4);
        *(float4*)(Wsm + jj * WPAD + gate * 512 + d4 * 4) = v;
    }
    float bhr = b_hh[s * G3 + j];
    float bhz = b_hh[s * G3 + 512 + j];
    float bhn = b_hh[s * G3 + 1024 + j];
    __syncthreads();

    const float4* wr = (const float4*)(Wsm + jl * WPAD) + kh * 64;
    const float4* wz = (const float4*)(Wsm + jl * WPAD + 512) + kh * 64;
    const float4* wn = (const float4*)(Wsm + jl * WPAD + 1024) + kh * 64;

    for (int t = 0; t < T_; t++) {
        const float* hin = (t == 0) ? (hidden + (size_t)s * B_ * H_)
                                    : (g_h[t & 1] + (size_t)s * B_ * H_);
        for (int i = tid; i < B_ * H_; i += 512)
            hsm[(i >> 9) * 516 + (i & 511)] = hin[i];
        __syncthreads();

        const float4* h4 = (const float4*)(hsm + b * 516) + kh * 64;
        float rx = 0, ry = 0, rz = 0, rw = 0;
        float zx = 0, zy = 0, zz = 0, zw = 0;
        float nx = 0, ny = 0, nz = 0, nw = 0;
#pragma unroll 8
        for (int d = 0; d < 64; d++) {
            float4 h = h4[d];
            float4 a = wr[d];
            float4 c = wz[d];
            float4 e = wn[d];
            rx += h.x * a.x; ry += h.y * a.y; rz += h.z * a.z; rw += h.w * a.w;
            zx += h.x * c.x; zy += h.y * c.y; zz += h.z * c.z; zw += h.w * c.w;
            nx += h.x * e.x; ny += h.y * e.y; nz += h.z * e.z; nw += h.w * e.w;
        }
        float pr = (rx + ry) + (rz + rw);
        float pz = (zx + zy) + (zz + zw);
        float pn = (nx + ny) + (nz + nw);

        if (kh) {
            int q = tid - 256;
            red[q * 3 + 0] = pr;
            red[q * 3 + 1] = pz;
            red[q * 3 + 2] = pn;
        }
        __syncthreads();

        if (!kh) {
            float ghr = pr + red[tid * 3 + 0] + bhr;
            float ghz = pz + red[tid * 3 + 1] + bhz;
            float ghn = pn + red[tid * 3 + 2] + bhn;

            int row = s * ROWS_PER_S + t * 16 + b;
            const float* gi = g_gi + (size_t)row * G3;
            float r = sigmoidf_(gi[j] + ghr);
            float z = sigmoidf_(gi[512 + j] + ghz);
            float n = tanhf(gi[1024 + j] + r * ghn);
            float hold = hsm[b * 516 + j];
            float hnew = (1.0f - z) * n + z * hold;

            g_h[(t + 1) & 1][((size_t)s * 16 + b) * 512 + j] = hnew;
            g_Ahi[(size_t)row * 1024 + 512 + j] = __float2half(hnew);
        }

        __threadfence();
        __syncthreads();
        if (tid == 0) {
            atomicAdd(&g_bar, 1u);
            unsigned target = 128u * (unsigned)(t + 1);
            while (*((volatile unsigned*)&g_bar) < target) { }
        }
        __syncthreads();
        __threadfence();
    }
}

// ===================== fp16 mma GEMM (BM128 x BN128, 256 thr, warp 64x32) ===
// Single-barrier pipeline: 4 stages, prefetch distance 2, one sync per chunk.
// MODE 2: out[1472,32000] = Ahi[.,1024] @ Wh^T + ctxlogit  (scatter) [1 pass]
// MODE 1: g_ctxlogit[64,32000] = Chi[.,512] @ Wc^T + fc_b            [1 pass]
// MODE 0: g_gi[s] = emb(hi+lo)[.,512] @ Wih(hi+lo)^T + gictx        [3 passes]
template <int MODE>
__global__ void __launch_bounds__(256, 2) k_fc(
    const float* __restrict__ bias, float* __restrict__ out) {
    constexpr int KCH = (MODE == 2) ? 32 : 16;
    constexpr int LDA = (MODE == 1) ? 512 : 1024;
    constexpr int LDB = (MODE == 2) ? 1024 : 512;
    constexpr bool SPLIT = (MODE == 0);
    constexpr int STAGE = SPLIT ? 32768 : 16384;

    extern __shared__ __align__(128) char sm_raw[];
    const uint32_t smem_base = smem_u32(sm_raw);
    const int tid = threadIdx.x;
    const int lane = tid & 31;
    const int w = tid >> 5;
    const int wm = w & 1;       // 0..1 : 64 rows each
    const int wn = w >> 1;      // 0..3 : 32 cols each
    const int m0 = blockIdx.x * 128;
    const int n0 = blockIdx.y * 128;
    const int s = (MODE == 0) ? blockIdx.z : 0;

    const __half* Ah;
    const __half* Al = nullptr;
    const __half* Bh;
    const __half* Bl = nullptr;
    if (MODE == 2)      { Ah = g_Ahi; Bh = g_Wh; }
    else if (MODE == 1) { Ah = g_Chi; Bh = g_Wc; }
    else {
        Ah = g_Ahi + (size_t)s * ROWS_PER_S * 1024;
        Al = g_Alo + (size_t)s * ROWS_PER_S * 1024;
        Bh = g_WihH + (size_t)s * G3 * 512;
        Bl = g_WihL + (size_t)s * G3 * 512;
    }

    float acc[4][4][4];
#pragma unroll
    for (int mt = 0; mt < 4; mt++)
#pragma unroll
        for (int nt = 0; nt < 4; nt++)
#pragma unroll
            for (int k = 0; k < 4; k++) acc[mt][nt][k] = 0.0f;

    auto load_stage = [&](int c) {
        int kk = c << 5;
        uint32_t st = smem_base + (c & 3) * STAGE;
#pragma unroll
        for (int it = 0; it < 2; it++) {
            int idx = tid + it * 256;
            int r = idx >> 2, g = idx & 3;
            uint32_t doff = r * 64 + ((g ^ ((r >> 1) & 3)) << 4);
            size_t aoff = (size_t)(m0 + r) * LDA + kk + g * 8;
            size_t boff = (size_t)(n0 + r) * LDB + kk + g * 8;
            CP_ASYNC16(st + doff, Ah + aoff);
            if (SPLIT) CP_ASYNC16(st + 8192 + doff, Al + aoff);
            CP_ASYNC16(st + (SPLIT ? 16384 : 8192) + doff, Bh + boff);
            if (SPLIT) CP_ASYNC16(st + 24576 + doff, Bl + boff);
        }
    };

    load_stage(0); CP_COMMIT();
    load_stage(1); CP_COMMIT();

    const int arow_b = wm * 64 + (lane & 15);
    const int aseg_b = lane >> 4;
    const int brow_b = wn * 32 + (lane & 7) + ((lane >> 4) << 3);
    const int bseg_b = (lane >> 3) & 1;

    for (int c = 0; c < KCH; c++) {
        if (c + 2 < KCH) { load_stage(c + 2); CP_COMMIT(); }
        int pend = ((KCH - 1 - c) < 2) ? (KCH - 1 - c) : 2;
        if (pend == 2)      asm volatile("cp.async.wait_group 2;" ::: "memory");
        else if (pend == 1) asm volatile("cp.async.wait_group 1;" ::: "memory");
        else                asm volatile("cp.async.wait_group 0;" ::: "memory");
        __syncthreads();

        uint32_t sa = smem_base + (c & 3) * STAGE;
        uint32_t sb = sa + (SPLIT ? 16384 : 8192);
#pragma unroll
        for (int ks = 0; ks < 2; ks++) {
            uint32_t ra_h[4][4], ra_l[4][4];
#pragma unroll
            for (int mt = 0; mt < 4; mt++) {
                int r = arow_b + mt * 16;
                int seg = 2 * ks + aseg_b;
                uint32_t doff = r * 64 + ((seg ^ ((r >> 1) & 3)) << 4);
                LDSM4(ra_h[mt][0], ra_h[mt][1], ra_h[mt][2], ra_h[mt][3], sa + doff);
                if (SPLIT)
                    LDSM4(ra_l[mt][0], ra_l[mt][1], ra_l[mt][2], ra_l[mt][3], sa + 8192 + doff);
            }
#pragma unroll
            for (int nt2 = 0; nt2 < 2; nt2++) {
                int r = brow_b + nt2 * 16;
                int seg = 2 * ks + bseg_b;
                uint32_t doff = r * 64 + ((seg ^ ((r >> 1) & 3)) << 4);
                uint32_t rb[4];
                LDSM4(rb[0], rb[1], rb[2], rb[3], sb + doff);
#pragma unroll
                for (int mt = 0; mt < 4; mt++) {
                    MMA16816H(acc[mt][nt2 * 2 + 0], ra_h[mt], rb[0], rb[1]);
                    MMA16816H(acc[mt][nt2 * 2 + 1], ra_h[mt], rb[2], rb[3]);
                }
                if (SPLIT) {
#pragma unroll
                    for (int mt = 0; mt < 4; mt++) {
                        MMA16816H(acc[mt][nt2 * 2 + 0], ra_l[mt], rb[0], rb[1]);
                        MMA16816H(acc[mt][nt2 * 2 + 1], ra_l[mt], rb[2], rb[3]);
                    }
                    uint32_t rbl[4];
                    LDSM4(rbl[0], rbl[1], rbl[2], rbl[3], sb + 8192 + doff);
#pragma unroll
                    for (int mt = 0; mt < 4; mt++) {
                        MMA16816H(acc[mt][nt2 * 2 + 0], ra_h[mt], rbl[0], rbl[1]);
                        MMA16816H(acc[mt][nt2 * 2 + 1], ra_h[mt], rbl[2], rbl[3]);
                    }
                }
            }
        }
        if (c + 1 < KCH) __syncthreads();
    }

    // epilogue
#pragma unroll
    for (int mt = 0; mt < 4; mt++) {
#pragma unroll
        for (int half = 0; half < 2; half++) {
            int R = m0 + wm * 64 + mt * 16 + (lane >> 2) + half * 8;
            if (MODE == 2) {
                if (R >= ROWS) continue;
                int s2 = R / ROWS_PER_S;
                int rr = R - s2 * ROWS_PER_S;
                int tt = rr >> 4;
                int b = rr & 15;
                float* dst = out + ((size_t)((b * S_ + s2) * L_ + tt + 1)) * V_;
                const float* ctx = g_ctxlogit + (size_t)(s2 * 16 + b) * V_;
#pragma unroll
                for (int nt = 0; nt < 4; nt++) {
                    int col = n0 + wn * 32 + nt * 8 + (lane & 3) * 2;
                    float2 cv = *(const float2*)(ctx + col);
                    float2 o;
                    o.x = acc[mt][nt][half * 2 + 0] + cv.x;
                    o.y = acc[mt][nt][half * 2 + 1] + cv.y;
                    *(float2*)(dst + col) = o;
                }
            } else if (MODE == 1) {
                if (R >= 64) continue;
                float* dst = g_ctxlogit + (size_t)R * V_;
#pragma unroll
                for (int nt = 0; nt < 4; nt++) {
                    int col = n0 + wn * 32 + nt * 8 + (lane & 3) * 2;
                    float2 bv = *(const float2*)(bias + col);
                    float2 o;
                    o.x = acc[mt][nt][half * 2 + 0] + bv.x;
                    o.y = acc[mt][nt][half * 2 + 1] + bv.y;
                    *(float2*)(dst + col) = o;
                }
            } else {
                if (R >= ROWS_PER_S) continue;
                int row = s * ROWS_PER_S + R;
                int b = R & 15;
                float* dst = g_gi + (size_t)row * G3;
                const float* add = g_gictx + (size_t)(s * 16 + b) * G3;
#pragma unroll
                for (int nt = 0; nt < 4; nt++) {
                    int col = n0 + wn * 32 + nt * 8 + (lane & 3) * 2;
                    float2 av = *(const float2*)(add + col);
                    float2 o;
                    o.x = acc[mt][nt][half * 2 + 0] + av.x;
                    o.y = acc[mt][nt][half * 2 + 1] + av.y;
                    *(float2*)(dst + col) = o;
                }
            }
        }
    }
}

#define SM_M0 (4 * 32768)
#define SM_M12 (4 * 16384)

// ===================== launch =====================
extern "C" void kernel_launch(void* const* d_in, const int* in_sizes, int n_in,
                              void* d_out, int out_size) {
    const int*   input  = (const int*)d_in[0];
    const float* hidden = (const float*)d_in[1];
    const float* agg    = (const float*)d_in[2];
    const float* emb    = (const float*)d_in[3];
    const float* W_ih   = (const float*)d_in[4];
    const float* W_hh   = (const float*)d_in[5];
    const float* b_ih   = (const float*)d_in[6];
    const float* b_hh   = (const float*)d_in[7];
    const float* fc_W   = (const float*)d_in[8];
    const float* fc_b   = (const float*)d_in[9];
    float* out = (float*)d_out;

    cudaFuncSetAttribute(k_fc<0>, cudaFuncAttributeMaxDynamicSharedMemorySize, SM_M0);
    cudaFuncSetAttribute(k_fc<1>, cudaFuncAttributeMaxDynamicSharedMemorySize, SM_M12);
    cudaFuncSetAttribute(k_fc<2>, cudaFuncAttributeMaxDynamicSharedMemorySize, SM_M12);
    cudaFuncSetAttribute(k_gru_scan, cudaFuncAttributeMaxDynamicSharedMemorySize, SCAN_SMEM);

    // 0: all independent prep work in one launch (concurrent blocks)
    k_prep<<<PB_TOTAL, 256>>>(input, hidden, agg, emb, W_ih, b_ih, fc_W, out);
    // 1: ctx_logit
    k_fc<1><<<dim3(1, V_ / 128), 256, SM_M12>>>(fc_b, nullptr);
    // 2: gi emb-part
    k_fc<0><<<dim3(3, G3 / 128, S_), 256, SM_M0>>>(nullptr, nullptr);
    // 3: GRU scan (profiled slot)
    k_gru_scan<<<128, 512, SCAN_SMEM>>>(hidden, W_hh, b_hh);
    // 4: main FC
    k_fc<2><<<dim3(MPAD / 128, V_ / 128), 256, SM_M12>>>(nullptr, out);
}

// round 17
// speedup vs baseline: 1.7015x; 1.0622x over previous
#include <cuda_runtime.h>
#include <cuda_fp16.h>
#include <math.h>
#include <stdint.h>

// Problem dims
#define S_ 4
#define B_ 16
#define T_ 23        // L-1
#define L_ 24
#define H_ 512
#define E_ 512
#define G3 1536      // 3H
#define V_ 32000
#define ROWS 1472    // S*T*B
#define ROWS_PER_S 368
#define MPAD 1536    // padded rows for tensor GEMM

// Scratch (device globals; no runtime allocation allowed)
__device__ float g_gi[ROWS * G3];         // gi_seq
__device__ float g_gictx[64 * G3];        // ctx part of gi (+ b_ih)
__device__ float g_h[2][S_ * B_ * H_];    // double-buffered hidden state
__device__ float g_ctxlogit[64 * V_];     // agg @ fc_W[:,1024:] + fc_b
__device__ __half g_Wh[(size_t)V_ * 1024];   // fc_W[:, :1024] fp16
__device__ __half g_Wc[(size_t)V_ * 512];    // fc_W[:, 1024:] fp16
__device__ __half g_Ahi[(size_t)MPAD * 1024]; // feats fp16 hi (pad rows stay zero)
__device__ __half g_Alo[(size_t)MPAD * 1024]; // emb fp16 lo (for gi GEMM only)
__device__ __half g_Chi[128 * 512];           // agg fp16 (rows 64.. stay zero)
__device__ __half g_WihH[(size_t)S_ * G3 * 512];  // W_ih[:, :512] fp16 hi
__device__ __half g_WihL[(size_t)S_ * G3 * 512];  // W_ih[:, :512] fp16 lo
__device__ unsigned g_bar;                // scan barrier counter (reset by prep)

static __device__ __forceinline__ float sigmoidf_(float x) {
    return 1.0f / (1.0f + expf(-x));
}

__device__ __forceinline__ uint32_t smem_u32(const void* p) {
    uint32_t a;
    asm("{ .reg .u64 t; cvta.to.shared.u64 t, %1; cvt.u32.u64 %0, t; }" : "=r"(a) : "l"(p));
    return a;
}

#define CP_ASYNC16(dst, src) \
    asm volatile("cp.async.cg.shared.global [%0], [%1], 16;" :: "r"(dst), "l"(src) : "memory")
#define CP_COMMIT() asm volatile("cp.async.commit_group;" ::: "memory")

#define LDSM4(r0, r1, r2, r3, addr) \
    asm volatile("ldmatrix.sync.aligned.m8n8.x4.shared.b16 {%0,%1,%2,%3}, [%4];" \
                 : "=r"(r0), "=r"(r1), "=r"(r2), "=r"(r3) : "r"(addr))

#define MMA16816H(d, a, b0, b1) \
    asm volatile("mma.sync.aligned.m16n8k16.row.col.f32.f16.f16.f32 " \
                 "{%0,%1,%2,%3}, {%4,%5,%6,%7}, {%8,%9}, {%0,%1,%2,%3};" \
                 : "+f"((d)[0]), "+f"((d)[1]), "+f"((d)[2]), "+f"((d)[3]) \
                 : "r"((a)[0]), "r"((a)[1]), "r"((a)[2]), "r"((a)[3]), \
                   "r"(b0), "r"(b1))

// split float4 -> fp16 hi (8B) + fp16 lo (8B)
__device__ __forceinline__ void fp16_split4(float4 v, uint2& hi, uint2& lo) {
    __half h0 = __float2half(v.x), h1 = __float2half(v.y);
    __half h2 = __float2half(v.z), h3 = __float2half(v.w);
    __half l0 = __float2half(v.x - __half2float(h0));
    __half l1 = __float2half(v.y - __half2float(h1));
    __half l2 = __float2half(v.z - __half2float(h2));
    __half l3 = __float2half(v.w - __half2float(h3));
    hi.x = (uint32_t)__half_as_ushort(h0) | ((uint32_t)__half_as_ushort(h1) << 16);
    hi.y = (uint32_t)__half_as_ushort(h2) | ((uint32_t)__half_as_ushort(h3) << 16);
    lo.x = (uint32_t)__half_as_ushort(l0) | ((uint32_t)__half_as_ushort(l1) << 16);
    lo.y = (uint32_t)__half_as_ushort(l2) | ((uint32_t)__half_as_ushort(l3) << 16);
}
__device__ __forceinline__ uint2 fp16_pack4(float4 v) {
    __half h0 = __float2half(v.x), h1 = __float2half(v.y);
    __half h2 = __float2half(v.z), h3 = __float2half(v.w);
    uint2 r;
    r.x = (uint32_t)__half_as_ushort(h0) | ((uint32_t)__half_as_ushort(h1) << 16);
    r.y = (uint32_t)__half_as_ushort(h2) | ((uint32_t)__half_as_ushort(h3) << 16);
    return r;
}

// ===================== fused prep kernel =====================
#define PB_CTX   0
#define PB_WSPL  768
#define PB_ONEH  48768
#define PB_WIH   56768
#define PB_GATH  59840
#define PB_CPREP 60576
#define PB_TOTAL 60608

__global__ void __launch_bounds__(256) k_prep(
    const int* __restrict__ input, const float* __restrict__ hidden,
    const float* __restrict__ agg, const float* __restrict__ emb,
    const float* __restrict__ W_ih, const float* __restrict__ b_ih,
    const float* __restrict__ fc_W, float* __restrict__ out) {
    int bid = blockIdx.x;
    int tid = threadIdx.x;

    if (bid < PB_WSPL) {
        // ---- ctx_gi
        int w = bid * 8 + (tid >> 5);
        int lane = tid & 31;
        int s = w / G3;
        int g = w - s * G3;
        const float* ctx = (s == 0) ? agg : (hidden + (size_t)s * B_ * H_);
        const float* wrow = W_ih + ((size_t)(s * G3) + g) * 1024 + 512;
        float acc[16];
#pragma unroll
        for (int b = 0; b < 16; b++) acc[b] = 0.0f;
        for (int d = lane; d < 512; d += 32) {
            float wv = wrow[d];
#pragma unroll
            for (int b = 0; b < 16; b++) acc[b] += wv * ctx[b * 512 + d];
        }
        float res = 0.0f;
#pragma unroll
        for (int b = 0; b < 16; b++) {
            float v = acc[b];
#pragma unroll
            for (int off = 16; off; off >>= 1) v += __shfl_xor_sync(0xffffffffu, v, off);
            if (lane == b) res = v;
        }
        if (lane < 16)
            g_gictx[(size_t)(s * 16 + lane) * G3 + g] = res + b_ih[s * G3 + g];
    } else if (bid < PB_ONEH) {
        // ---- wsplit (+ reset scan barrier)
        long idx = (long)(bid - PB_WSPL) * 256 + tid;
        if (idx == 0) g_bar = 0;
        if (idx < (long)V_ * 384) {
            int row = (int)(idx / 384);
            int c4 = (int)(idx - (long)row * 384);
            int col = c4 * 4;
            float4 v = *(const float4*)(fc_W + (size_t)row * G3 + col);
            uint2 h = fp16_pack4(v);
            if (col < 1024)
                *(uint2*)(g_Wh + (size_t)row * 1024 + col) = h;
            else
                *(uint2*)(g_Wc + (size_t)row * 512 + (col - 1024)) = h;
        }
    } else if (bid < PB_WIH) {
        // ---- onehot
        long i = (long)(bid - PB_ONEH) * 256 + tid;
        if (i < (long)64 * V_) {
            int p = (int)(i / V_);
            int v = (int)(i - (long)p * V_);
            out[(size_t)p * L_ * V_ + v] = (v == 1) ? 1.0f : 0.0f;
        }
    } else if (bid < PB_GATH) {
        // ---- wihsplit
        int idx = (bid - PB_WIH) * 256 + tid;
        if (idx < S_ * G3 * 128) {
            int row = idx >> 7;
            int c4 = idx & 127;
            float4 v = *(const float4*)(W_ih + (size_t)row * 1024 + c4 * 4);
            uint2 hi, lo;
            fp16_split4(v, hi, lo);
            *(uint2*)(g_WihH + (size_t)row * 512 + c4 * 4) = hi;
            *(uint2*)(g_WihL + (size_t)row * 512 + c4 * 4) = lo;
        }
    } else if (bid < PB_CPREP) {
        // ---- gather
        int row = (bid - PB_GATH) * 2 + (tid >> 7);
        int t2 = tid & 127;
        if (row < ROWS) {
            int s = row / ROWS_PER_S;
            int rr = row - s * ROWS_PER_S;
            int t = rr >> 4;
            int b = rr & 15;
            int tok = input[(b * S_ + s) * L_ + t];
            float4 v = ((const float4*)(emb + (size_t)tok * E_))[t2];
            uint2 hi, lo;
            fp16_split4(v, hi, lo);
            *(uint2*)(g_Ahi + (size_t)row * 1024 + t2 * 4) = hi;
            *(uint2*)(g_Alo + (size_t)row * 1024 + t2 * 4) = lo;
        }
    } else {
        // ---- cprep
        int row = (bid - PB_CPREP) * 2 + (tid >> 7);
        int t2 = tid & 127;
        if (row < 64) {
            float4 v = ((const float4*)(agg + (size_t)row * 512))[t2];
            *(uint2*)(g_Chi + (size_t)row * 512 + t2 * 4) = fp16_pack4(v);
        }
    }
}

// ===================== persistent GRU scan (512 thr, K-split, reg double-buf) ====
#define WPAD 1540
#define SCAN_SMEM ((16 * WPAD + 16 * 516 + 768) * 4)

__global__ void __launch_bounds__(512) k_gru_scan(
    const float* __restrict__ hidden, const float* __restrict__ W_hh,
    const float* __restrict__ b_hh) {
    extern __shared__ float sm[];
    float* Wsm = sm;                        // [16][WPAD]
    float* hsm = sm + 16 * WPAD;            // [16][516]
    float* red = sm + 16 * WPAD + 16 * 516; // [256][3]
    int bid = blockIdx.x;
    int s = bid >> 5, jt = bid & 31;
    int tid = threadIdx.x;
    int b = tid & 15, jl = (tid >> 4) & 15, kh = tid >> 8;
    int j = jt * 16 + jl;

    for (int i = tid; i < 16 * 3 * 128; i += 512) {
        int jj = i / 384;
        int rem = i - jj * 384;
        int gate = rem >> 7;
        int d4 = rem & 127;
        float4 v = *(const float4*)(W_hh +
            ((size_t)(s * G3 + gate * 512 + jt * 16 + jj)) * 512 + d4 * 4);
        *(float4*)(Wsm + jj * WPAD + gate * 512 + d4 * 4) = v;
    }
    float bhr = b_hh[s * G3 + j];
    float bhz = b_hh[s * G3 + 512 + j];
    float bhn = b_hh[s * G3 + 1024 + j];
    __syncthreads();

    const float4* wr = (const float4*)(Wsm + jl * WPAD) + kh * 64;
    const float4* wz = (const float4*)(Wsm + jl * WPAD + 512) + kh * 64;
    const float4* wn = (const float4*)(Wsm + jl * WPAD + 1024) + kh * 64;

    for (int t = 0; t < T_; t++) {
        // h fill via L2-only loads (no L1 staleness -> no fences needed)
        const float4* hin4 = (const float4*)((t == 0)
            ? (hidden + (size_t)s * B_ * H_) : (g_h[t & 1] + (size_t)s * B_ * H_));
#pragma unroll
        for (int it = 0; it < 4; it++) {
            int i = tid + it * 512;
            float4 v = __ldcg(hin4 + i);
            *(float4*)&hsm[(i >> 7) * 516 + (i & 127) * 4] = v;
        }
        // prefetch gi (overlaps fill latency; L1-cacheable, stable during scan)
        int row = s * ROWS_PER_S + t * 16 + b;
        float gir = 0.f, giz = 0.f, gin0 = 0.f;
        if (!kh) {
            const float* gi = g_gi + (size_t)row * G3;
            gir = gi[j]; giz = gi[512 + j]; gin0 = gi[1024 + j];
        }
        __syncthreads();

        const float4* h4 = (const float4*)(hsm + b * 516) + kh * 64;
        float rx = 0, ry = 0, rz = 0, rw = 0;
        float zx = 0, zy = 0, zz = 0, zw = 0;
        float nx = 0, ny = 0, nz = 0, nw = 0;
        // register double-buffer: blocks of 2 iters, batched 8x LDS.128
        float4 bh[2][2], ba[2][2], bc[2][2], be[2][2];
        bh[0][0] = h4[0]; bh[0][1] = h4[1];
        ba[0][0] = wr[0]; ba[0][1] = wr[1];
        bc[0][0] = wz[0]; bc[0][1] = wz[1];
        be[0][0] = wn[0]; be[0][1] = wn[1];
#pragma unroll
        for (int blk = 0; blk < 32; blk++) {
            int cur = blk & 1, nxt = cur ^ 1;
            if (blk < 31) {
                int d = (blk + 1) * 2;
                bh[nxt][0] = h4[d]; bh[nxt][1] = h4[d + 1];
                ba[nxt][0] = wr[d]; ba[nxt][1] = wr[d + 1];
                bc[nxt][0] = wz[d]; bc[nxt][1] = wz[d + 1];
                be[nxt][0] = wn[d]; be[nxt][1] = wn[d + 1];
            }
#pragma unroll
            for (int u = 0; u < 2; u++) {
                float4 h = bh[cur][u], a = ba[cur][u], c = bc[cur][u], e = be[cur][u];
                rx += h.x * a.x; ry += h.y * a.y; rz += h.z * a.z; rw += h.w * a.w;
                zx += h.x * c.x; zy += h.y * c.y; zz += h.z * c.z; zw += h.w * c.w;
                nx += h.x * e.x; ny += h.y * e.y; nz += h.z * e.z; nw += h.w * e.w;
            }
        }
        float pr = (rx + ry) + (rz + rw);
        float pz = (zx + zy) + (zz + zw);
        float pn = (nx + ny) + (nz + nw);

        if (kh) {
            int q = tid - 256;
            red[q * 3 + 0] = pr;
            red[q * 3 + 1] = pz;
            red[q * 3 + 2] = pn;
        }
        __syncthreads();

        if (!kh) {
            float ghr = pr + red[tid * 3 + 0] + bhr;
            float ghz = pz + red[tid * 3 + 1] + bhz;
            float ghn = pn + red[tid * 3 + 2] + bhn;

            float r = sigmoidf_(gir + ghr);
            float z = sigmoidf_(giz + ghz);
            float n = tanhf(gin0 + r * ghn);
            float hold = hsm[b * 516 + j];
            float hnew = (1.0f - z) * n + z * hold;

            g_h[(t + 1) & 1][((size_t)s * 16 + b) * 512 + j] = hnew;
            g_Ahi[(size_t)row * 1024 + 512 + j] = __float2half(hnew);
        }

        __syncthreads();   // all h stores program-ordered before tid0's release
        if (tid == 0) {
            asm volatile("red.release.gpu.global.add.u32 [%0], %1;"
                         :: "l"(&g_bar), "r"(1u) : "memory");
            unsigned target = 128u * (unsigned)(t + 1);
            unsigned v;
            do {
                asm volatile("ld.acquire.gpu.global.u32 %0, [%1];"
                             : "=r"(v) : "l"(&g_bar) : "memory");
            } while (v < target);
        }
        __syncthreads();
    }
}

// ===================== fp16 mma GEMM (BM128 x BN128, 256 thr, warp 64x32) ===
// MODE 2: out[1472,32000] = Ahi[.,1024] @ Wh^T + ctxlogit  (scatter) [1 pass]
// MODE 1: g_ctxlogit[64,32000] = Chi[.,512] @ Wc^T + fc_b            [1 pass]
// MODE 0: g_gi[s] = emb(hi+lo)[.,512] @ Wih(hi+lo)^T + gictx        [3 passes]
template <int MODE>
__global__ void __launch_bounds__(256, 2) k_fc(
    const float* __restrict__ bias, float* __restrict__ out) {
    constexpr int KCH = (MODE == 2) ? 32 : 16;
    constexpr int LDA = (MODE == 1) ? 512 : 1024;
    constexpr int LDB = (MODE == 2) ? 1024 : 512;
    constexpr bool SPLIT = (MODE == 0);
    constexpr int STAGE = SPLIT ? 32768 : 16384;

    extern __shared__ __align__(128) char sm_raw[];
    const uint32_t smem_base = smem_u32(sm_raw);
    const int tid = threadIdx.x;
    const int lane = tid & 31;
    const int w = tid >> 5;
    const int wm = w & 1;       // 0..1 : 64 rows each
    const int wn = w >> 1;      // 0..3 : 32 cols each
    const int m0 = blockIdx.x * 128;
    const int n0 = blockIdx.y * 128;
    const int s = (MODE == 0) ? blockIdx.z : 0;

    const __half* Ah;
    const __half* Al = nullptr;
    const __half* Bh;
    const __half* Bl = nullptr;
    if (MODE == 2)      { Ah = g_Ahi; Bh = g_Wh; }
    else if (MODE == 1) { Ah = g_Chi; Bh = g_Wc; }
    else {
        Ah = g_Ahi + (size_t)s * ROWS_PER_S * 1024;
        Al = g_Alo + (size_t)s * ROWS_PER_S * 1024;
        Bh = g_WihH + (size_t)s * G3 * 512;
        Bl = g_WihL + (size_t)s * G3 * 512;
    }

    float acc[4][4][4];
#pragma unroll
    for (int mt = 0; mt < 4; mt++)
#pragma unroll
        for (int nt = 0; nt < 4; nt++)
#pragma unroll
            for (int k = 0; k < 4; k++) acc[mt][nt][k] = 0.0f;

    auto load_stage = [&](int c) {
        int kk = c << 5;
        uint32_t st = smem_base + (c & 3) * STAGE;
#pragma unroll
        for (int it = 0; it < 2; it++) {
            int idx = tid + it * 256;
            int r = idx >> 2, g = idx & 3;
            uint32_t doff = r * 64 + ((g ^ ((r >> 1) & 3)) << 4);
            size_t aoff = (size_t)(m0 + r) * LDA + kk + g * 8;
            size_t boff = (size_t)(n0 + r) * LDB + kk + g * 8;
            CP_ASYNC16(st + doff, Ah + aoff);
            if (SPLIT) CP_ASYNC16(st + 8192 + doff, Al + aoff);
            CP_ASYNC16(st + (SPLIT ? 16384 : 8192) + doff, Bh + boff);
            if (SPLIT) CP_ASYNC16(st + 24576 + doff, Bl + boff);
        }
    };

    load_stage(0); CP_COMMIT();
    load_stage(1); CP_COMMIT();

    const int arow_b = wm * 64 + (lane & 15);
    const int aseg_b = lane >> 4;
    const int brow_b = wn * 32 + (lane & 7) + ((lane >> 4) << 3);
    const int bseg_b = (lane >> 3) & 1;

    for (int c = 0; c < KCH; c++) {
        if (c + 2 < KCH) { load_stage(c + 2); CP_COMMIT(); }
        int pend = ((KCH - 1 - c) < 2) ? (KCH - 1 - c) : 2;
        if (pend == 2)      asm volatile("cp.async.wait_group 2;" ::: "memory");
        else if (pend == 1) asm volatile("cp.async.wait_group 1;" ::: "memory");
        else                asm volatile("cp.async.wait_group 0;" ::: "memory");
        __syncthreads();

        uint32_t sa = smem_base + (c & 3) * STAGE;
        uint32_t sb = sa + (SPLIT ? 16384 : 8192);
#pragma unroll
        for (int ks = 0; ks < 2; ks++) {
            uint32_t ra_h[4][4], ra_l[4][4];
#pragma unroll
            for (int mt = 0; mt < 4; mt++) {
                int r = arow_b + mt * 16;
                int seg = 2 * ks + aseg_b;
                uint32_t doff = r * 64 + ((seg ^ ((r >> 1) & 3)) << 4);
                LDSM4(ra_h[mt][0], ra_h[mt][1], ra_h[mt][2], ra_h[mt][3], sa + doff);
                if (SPLIT)
                    LDSM4(ra_l[mt][0], ra_l[mt][1], ra_l[mt][2], ra_l[mt][3], sa + 8192 + doff);
            }
#pragma unroll
            for (int nt2 = 0; nt2 < 2; nt2++) {
                int r = brow_b + nt2 * 16;
                int seg = 2 * ks + bseg_b;
                uint32_t doff = r * 64 + ((seg ^ ((r >> 1) & 3)) << 4);
                uint32_t rb[4];
                LDSM4(rb[0], rb[1], rb[2], rb[3], sb + doff);
#pragma unroll
                for (int mt = 0; mt < 4; mt++) {
                    MMA16816H(acc[mt][nt2 * 2 + 0], ra_h[mt], rb[0], rb[1]);
                    MMA16816H(acc[mt][nt2 * 2 + 1], ra_h[mt], rb[2], rb[3]);
                }
                if (SPLIT) {
#pragma unroll
                    for (int mt = 0; mt < 4; mt++) {
                        MMA16816H(acc[mt][nt2 * 2 + 0], ra_l[mt], rb[0], rb[1]);
                        MMA16816H(acc[mt][nt2 * 2 + 1], ra_l[mt], rb[2], rb[3]);
                    }
                    uint32_t rbl[4];
                    LDSM4(rbl[0], rbl[1], rbl[2], rbl[3], sb + 8192 + doff);
#pragma unroll
                    for (int mt = 0; mt < 4; mt++) {
                        MMA16816H(acc[mt][nt2 * 2 + 0], ra_h[mt], rbl[0], rbl[1]);
                        MMA16816H(acc[mt][nt2 * 2 + 1], ra_h[mt], rbl[2], rbl[3]);
                    }
                }
            }
        }
        if (c + 1 < KCH) __syncthreads();
    }

    // epilogue
#pragma unroll
    for (int mt = 0; mt < 4; mt++) {
#pragma unroll
        for (int half = 0; half < 2; half++) {
            int R = m0 + wm * 64 + mt * 16 + (lane >> 2) + half * 8;
            if (MODE == 2) {
                if (R >= ROWS) continue;
                int s2 = R / ROWS_PER_S;
                int rr = R - s2 * ROWS_PER_S;
                int tt = rr >> 4;
                int b = rr & 15;
                float* dst = out + ((size_t)((b * S_ + s2) * L_ + tt + 1)) * V_;
                const float* ctx = g_ctxlogit + (size_t)(s2 * 16 + b) * V_;
#pragma unroll
                for (int nt = 0; nt < 4; nt++) {
                    int col = n0 + wn * 32 + nt * 8 + (lane & 3) * 2;
                    float2 cv = *(const float2*)(ctx + col);
                    float2 o;
                    o.x = acc[mt][nt][half * 2 + 0] + cv.x;
                    o.y = acc[mt][nt][half * 2 + 1] + cv.y;
                    *(float2*)(dst + col) = o;
                }
            } else if (MODE == 1) {
                if (R >= 64) continue;
                float* dst = g_ctxlogit + (size_t)R * V_;
#pragma unroll
                for (int nt = 0; nt < 4; nt++) {
                    int col = n0 + wn * 32 + nt * 8 + (lane & 3) * 2;
                    float2 bv = *(const float2*)(bias + col);
                    float2 o;
                    o.x = acc[mt][nt][half * 2 + 0] + bv.x;
                    o.y = acc[mt][nt][half * 2 + 1] + bv.y;
                    *(float2*)(dst + col) = o;
                }
            } else {
                if (R >= ROWS_PER_S) continue;
                int row = s * ROWS_PER_S + R;
                int b = R & 15;
                float* dst = g_gi + (size_t)row * G3;
                const float* add = g_gictx + (size_t)(s * 16 + b) * G3;
#pragma unroll
                for (int nt = 0; nt < 4; nt++) {
                    int col = n0 + wn * 32 + nt * 8 + (lane & 3) * 2;
                    float2 av = *(const float2*)(add + col);
                    float2 o;
                    o.x = acc[mt][nt][half * 2 + 0] + av.x;
                    o.y = acc[mt][nt][half * 2 + 1] + av.y;
                    *(float2*)(dst + col) = o;
                }
            }
        }
    }
}

#define SM_M0 (4 * 32768)
#define SM_M12 (4 * 16384)

// ===================== launch =====================
extern "C" void kernel_launch(void* const* d_in, const int* in_sizes, int n_in,
                              void* d_out, int out_size) {
    const int*   input  = (const int*)d_in[0];
    const float* hidden = (const float*)d_in[1];
    const float* agg    = (const float*)d_in[2];
    const float* emb    = (const float*)d_in[3];
    const float* W_ih   = (const float*)d_in[4];
    const float* W_hh   = (const float*)d_in[5];
    const float* b_ih   = (const float*)d_in[6];
    const float* b_hh   = (const float*)d_in[7];
    const float* fc_W   = (const float*)d_in[8];
    const float* fc_b   = (const float*)d_in[9];
    float* out = (float*)d_out;

    cudaFuncSetAttribute(k_fc<0>, cudaFuncAttributeMaxDynamicSharedMemorySize, SM_M0);
    cudaFuncSetAttribute(k_fc<1>, cudaFuncAttributeMaxDynamicSharedMemorySize, SM_M12);
    cudaFuncSetAttribute(k_fc<2>, cudaFuncAttributeMaxDynamicSharedMemorySize, SM_M12);
    cudaFuncSetAttribute(k_gru_scan, cudaFuncAttributeMaxDynamicSharedMemorySize, SCAN_SMEM);

    // 0: all independent prep work in one launch (concurrent blocks)
    k_prep<<<PB_TOTAL, 256>>>(input, hidden, agg, emb, W_ih, b_ih, fc_W, out);
    // 1: ctx_logit
    k_fc<1><<<dim3(1, V_ / 128), 256, SM_M12>>>(fc_b, nullptr);
    // 2: gi emb-part
    k_fc<0><<<dim3(3, G3 / 128, S_), 256, SM_M0>>>(nullptr, nullptr);
    // 3: GRU scan (profiled slot)
    k_gru_scan<<<128, 512, SCAN_SMEM>>>(hidden, W_hh, b_hh);
    // 4: main FC
    k_fc<2><<<dim3(MPAD / 128, V_ / 128), 256, SM_M12>>>(nullptr, out);
}